// round 7
// baseline (speedup 1.0000x reference)
#include <cuda_runtime.h>
#include <mma.h>
#include <cstdint>

using namespace nvcuda;

#define DIMX      1024
#define D_INNER   2048
#define NHEADS    16
#define HEADDIM   128
#define D_STATE   64
#define CONV_DIM  2176      // D_INNER + 2*D_STATE
#define D_IN_PROJ 4240      // 2*D_INNER + 2*D_STATE + NHEADS
#define CHUNKL    256
#define NCHUNK    16        // per batch (4096/256)
#define BATCHN    2
#define SEQLENN   4096
#define NT        8192      // BATCH*SEQLEN tokens
#define NBC       32        // BATCH*NCHUNK

// ---------------- scratch (static device memory; no runtime allocation) ----
__device__ float g_w1n[(size_t)D_IN_PROJ * DIMX];        // normalized in_proj (scale folded, tf32-rounded)
__device__ float g_w2n[(size_t)DIMX * D_INNER];          // normalized out_proj (tf32-rounded)
__device__ float g_uln[(size_t)NT * DIMX];               // layernormed input (tf32-rounded)
__device__ float g_zx [(size_t)NT * D_IN_PROJ];          // zxbcdt
__device__ float g_xbc[(size_t)NT * CONV_DIM];           // conv+silu output
__device__ float g_dt [(size_t)NT * NHEADS];
__device__ float g_cum[(size_t)NT * NHEADS];             // in-chunk inclusive cumsum of dt*A
__device__ float g_scores[(size_t)NBC * CHUNKL * CHUNKL];
__device__ float g_states[(size_t)NBC * NHEADS * HEADDIM * D_STATE];
__device__ float g_prev  [(size_t)NBC * NHEADS * HEADDIM * D_STATE];
__device__ float g_y  [(size_t)NT * D_INNER];            // y, then g (in place, tf32-rounded)

// ---------------- helpers ---------------------------------------------------
__device__ __forceinline__ float to_tf32(float x) {
    float r;
    asm("cvt.rna.tf32.f32 %0, %1;" : "=f"(r) : "f"(x));
    return r;
}

__device__ __forceinline__ void cp_async16(void* smem_dst, const void* gmem_src, int src_sz) {
    uint32_t s = (uint32_t)__cvta_generic_to_shared(smem_dst);
    asm volatile("cp.async.cg.shared.global [%0], [%1], 16, %2;"
                 :: "r"(s), "l"(gmem_src), "r"(src_sz));
}
__device__ __forceinline__ void cp_commit() { asm volatile("cp.async.commit_group;"); }
template <int N> __device__ __forceinline__ void cp_wait() {
    asm volatile("cp.async.wait_group %0;" :: "n"(N));
}

__device__ __forceinline__ void block_reduce2(float& a, float& b) {
    __shared__ float sa[32], sb[32];
    int lane = threadIdx.x & 31, w = threadIdx.x >> 5;
    #pragma unroll
    for (int o = 16; o; o >>= 1) {
        a += __shfl_down_sync(0xffffffffu, a, o);
        b += __shfl_down_sync(0xffffffffu, b, o);
    }
    if (lane == 0) { sa[w] = a; sb[w] = b; }
    __syncthreads();
    if (w == 0) {
        int nw = blockDim.x >> 5;
        a = (lane < nw) ? sa[lane] : 0.f;
        b = (lane < nw) ? sb[lane] : 0.f;
        #pragma unroll
        for (int o = 16; o; o >>= 1) {
            a += __shfl_down_sync(0xffffffffu, a, o);
            b += __shfl_down_sync(0xffffffffu, b, o);
        }
        if (lane == 0) { sa[0] = a; sb[0] = b; }
    }
    __syncthreads();
    a = sa[0]; b = sb[0];
}

// ---------------- weight l2-normalization (tf32-rounded output) -------------
__global__ void __launch_bounds__(256) l2norm_rows_k(const float* __restrict__ W,
                                                     float* __restrict__ out,
                                                     int K, float extra) {
    int row = blockIdx.x;
    const float* src = W + (size_t)row * K;
    float ss = 0.f, dummy = 0.f;
    for (int i = threadIdx.x; i < K; i += blockDim.x) { float v = src[i]; ss += v * v; }
    block_reduce2(ss, dummy);
    float scale = extra / fmaxf(sqrtf(ss), 1e-6f);
    float* dst = out + (size_t)row * K;
    for (int i = threadIdx.x; i < K; i += blockDim.x) dst[i] = to_tf32(src[i] * scale);
}

// ---------------- input layernorm (tf32-rounded output) ---------------------
__global__ void __launch_bounds__(256) layernorm_k(const float* __restrict__ u,
                                                   const float* __restrict__ w,
                                                   const float* __restrict__ b) {
    int t = blockIdx.x;
    const float* x = u + (size_t)t * DIMX;
    float v[4]; float s = 0.f, s2 = 0.f;
    #pragma unroll
    for (int k = 0; k < 4; k++) {
        v[k] = x[threadIdx.x + k * 256];
        s += v[k]; s2 += v[k] * v[k];
    }
    block_reduce2(s, s2);
    float mu = s * (1.f / DIMX);
    float var = s2 * (1.f / DIMX) - mu * mu;
    float inv = rsqrtf(var + 1e-5f);
    float* o = g_uln + (size_t)t * DIMX;
    #pragma unroll
    for (int k = 0; k < 4; k++) {
        int i = threadIdx.x + k * 256;
        o[i] = to_tf32((v[k] - mu) * inv * w[i] + b[i]);
    }
}

// ---------------- tf32 GEMM: C[M,N] = A[M,K] * B[N,K]^T ----------------------
// 256x128 block tile, BK=32, 3-stage cp.async pipeline, 16 warps (4x4),
// warp tile 64x32 (4x2 wmma frags). One __syncthreads per K-tile.
#define GSTAGES 3
#define ASF (256 * 36)
#define BSF (128 * 36)
#define STAGE_F (ASF + BSF)
#define GEMM_SMEM (GSTAGES * STAGE_F * 4)

__device__ __forceinline__ void gemm_load_stage(float* stage,
                                                const float* __restrict__ A,
                                                const float* __restrict__ B,
                                                int bm, int bn, int k0,
                                                int N, int K, int tid) {
    float* As = stage;
    float* Bs = stage + ASF;
    #pragma unroll
    for (int u = 0; u < 4; u++) {           // A: 256x32 = 2048 float4
        int idx = tid + u * 512;
        int r = idx >> 3, cc = (idx & 7) * 4;
        cp_async16(&As[r * 36 + cc], A + (size_t)(bm + r) * K + k0 + cc, 16);
    }
    #pragma unroll
    for (int u = 0; u < 2; u++) {           // B: 128x32 = 1024 float4
        int idx = tid + u * 512;
        int r = idx >> 3, cc = (idx & 7) * 4;
        int brow = bn + r;
        int safe = (brow < N) ? brow : (N - 1);
        cp_async16(&Bs[r * 36 + cc], B + (size_t)safe * K + k0 + cc, (brow < N) ? 16 : 0);
    }
    cp_commit();
}

__global__ void __launch_bounds__(512, 1) gemm_tf32_nt(const float* __restrict__ A,
                                                       const float* __restrict__ B,
                                                       float* __restrict__ C,
                                                       int M, int N, int K) {
    extern __shared__ float sm[];
    int bm = blockIdx.y * 256;
    int bn = blockIdx.x * 128;
    int tid = threadIdx.x;
    int warp = tid >> 5;
    int wm = (warp >> 2) * 64;               // 4 M-groups
    int wn = (warp & 3) * 32;                // 4 N-groups

    wmma::fragment<wmma::accumulator, 16, 16, 8, float> c[4][2];
    #pragma unroll
    for (int i = 0; i < 4; i++)
        #pragma unroll
        for (int j = 0; j < 2; j++) wmma::fill_fragment(c[i][j], 0.0f);

    int kTiles = K >> 5;
    #pragma unroll
    for (int s = 0; s < GSTAGES - 1; s++)
        gemm_load_stage(sm + s * STAGE_F, A, B, bm, bn, s * 32, N, K, tid);

    for (int kt = 0; kt < kTiles; kt++) {
        cp_wait<GSTAGES - 2>();
        __syncthreads();
        int nk = kt + GSTAGES - 1;
        if (nk < kTiles)
            gemm_load_stage(sm + (nk % GSTAGES) * STAGE_F, A, B, bm, bn,
                            nk * 32, N, K, tid);

        const float* stage = sm + (kt % GSTAGES) * STAGE_F;
        const float* As = stage;
        const float* Bs = stage + ASF;
        #pragma unroll
        for (int ks = 0; ks < 32; ks += 8) {
            wmma::fragment<wmma::matrix_a, 16, 16, 8, wmma::precision::tf32, wmma::row_major> a[4];
            wmma::fragment<wmma::matrix_b, 16, 16, 8, wmma::precision::tf32, wmma::col_major> bf[2];
            #pragma unroll
            for (int i = 0; i < 4; i++)
                wmma::load_matrix_sync(a[i], As + (wm + i * 16) * 36 + ks, 36);
            #pragma unroll
            for (int j = 0; j < 2; j++)
                wmma::load_matrix_sync(bf[j], Bs + (wn + j * 16) * 36 + ks, 36);
            #pragma unroll
            for (int i = 0; i < 4; i++)
                #pragma unroll
                for (int j = 0; j < 2; j++)
                    wmma::mma_sync(c[i][j], a[i], bf[j], c[i][j]);
        }
    }
    __syncthreads();
    #pragma unroll
    for (int i = 0; i < 4; i++)
        #pragma unroll
        for (int j = 0; j < 2; j++) {
            int cn = bn + wn + j * 16;
            if (cn < N)   // N is a multiple of 16 -> fragment fully valid
                wmma::store_matrix_sync(C + (size_t)(bm + wm + i * 16) * N + cn,
                                        c[i][j], N, wmma::mem_row_major);
        }
}

// ---------------- dt = softplus(raw + bias); cum = cumsum(dt*A) per chunk ----
__global__ void __launch_bounds__(256) dtcum_k(const float* __restrict__ dt_bias,
                                               const float* __restrict__ A_log) {
    int h = blockIdx.x & 15, bc = blockIdx.x >> 4;
    int t = bc * CHUNKL + threadIdx.x;
    float raw = g_zx[(size_t)t * D_IN_PROJ + (D_INNER + CONV_DIM) + h] + dt_bias[h];
    float dt = (raw > 20.f) ? raw : log1pf(expf(raw));
    g_dt[t * NHEADS + h] = dt;
    float dA = dt * (-expf(A_log[h]));
    __shared__ float sc[CHUNKL];
    sc[threadIdx.x] = dA;
    __syncthreads();
    for (int off = 1; off < CHUNKL; off <<= 1) {
        float add = (threadIdx.x >= off) ? sc[threadIdx.x - off] : 0.f;
        __syncthreads();
        sc[threadIdx.x] += add;
        __syncthreads();
    }
    g_cum[t * NHEADS + h] = sc[threadIdx.x];
}

// ---------------- causal depthwise conv (w=4) + SiLU -------------------------
__global__ void __launch_bounds__(256) conv_silu_k(const float* __restrict__ cw,
                                                   const float* __restrict__ cb) {
    int t = blockIdx.x;
    int ch = blockIdx.y * 256 + threadIdx.x;
    if (ch >= CONV_DIM) return;
    int l = t & (SEQLENN - 1);
    float acc = cb[ch];
    #pragma unroll
    for (int j = 0; j < 4; j++) {
        int ll = l - 3 + j;
        if (ll >= 0)
            acc = fmaf(cw[ch * 4 + j], g_zx[(size_t)(t - 3 + j) * D_IN_PROJ + D_INNER + ch], acc);
    }
    float sv = acc / (1.f + __expf(-acc));
    g_xbc[(size_t)t * CONV_DIM + ch] = sv;
}

// ---------------- scores[i,j] = C_i . B_j (lower triangle tiles only) --------
__global__ void __launch_bounds__(256) scores_k() {
    int bc = blockIdx.x;
    int i0 = blockIdx.y * 32;
    int t0 = bc * CHUNKL;
    __shared__ float Cs[32][65];
    __shared__ float Bs[64][65];
    for (int idx = threadIdx.x; idx < 32 * 64; idx += 256) {
        int r = idx >> 6, n = idx & 63;
        Cs[r][n] = g_xbc[(size_t)(t0 + i0 + r) * CONV_DIM + D_INNER + D_STATE + n];
    }
    for (int j0 = 0; j0 <= i0 + 31; j0 += 64) {
        __syncthreads();
        for (int idx = threadIdx.x; idx < 64 * 64; idx += 256) {
            int r = idx >> 6, n = idx & 63;
            Bs[r][n] = g_xbc[(size_t)(t0 + j0 + r) * CONV_DIM + D_INNER + n];
        }
        __syncthreads();
        #pragma unroll
        for (int q = 0; q < 8; q++) {
            int o = threadIdx.x + q * 256;
            int ii = o >> 6, jj = o & 63;
            float acc = 0.f;
            #pragma unroll
            for (int n = 0; n < 64; n++) acc = fmaf(Cs[ii][n], Bs[jj][n], acc);
            g_scores[(size_t)bc * 65536 + (size_t)(i0 + ii) * 256 + (j0 + jj)] = acc;
        }
    }
}

// ---------------- chunk-end states: state[p,n] = sum_l x[l,p]*dt*decay*B[l,n]-
__global__ void __launch_bounds__(256) states_k() {
    int h = blockIdx.x & 15, bc = blockIdx.x >> 4;
    int t0 = bc * CHUNKL;
    float cum_last = g_cum[(t0 + CHUNKL - 1) * NHEADS + h];
    int n = threadIdx.x & 63;
    int pbase = (threadIdx.x >> 6) * 32;
    float acc[32];
    #pragma unroll
    for (int p = 0; p < 32; p++) acc[p] = 0.f;
    __shared__ float xs[32][128];
    __shared__ float Bs[32][65];
    __shared__ float coef[32];
    for (int l0 = 0; l0 < CHUNKL; l0 += 32) {
        __syncthreads();
        for (int idx = threadIdx.x; idx < 32 * 128; idx += 256) {
            int r = idx >> 7, p = idx & 127;
            xs[r][p] = g_xbc[(size_t)(t0 + l0 + r) * CONV_DIM + h * HEADDIM + p];
        }
        for (int idx = threadIdx.x; idx < 32 * 64; idx += 256) {
            int r = idx >> 6, nn = idx & 63;
            Bs[r][nn] = g_xbc[(size_t)(t0 + l0 + r) * CONV_DIM + D_INNER + nn];
        }
        if (threadIdx.x < 32) {
            int tt = t0 + l0 + threadIdx.x;
            coef[threadIdx.x] = g_dt[tt * NHEADS + h] * __expf(cum_last - g_cum[tt * NHEADS + h]);
        }
        __syncthreads();
        #pragma unroll 4
        for (int l = 0; l < 32; l++) {
            float bn = Bs[l][n] * coef[l];
            #pragma unroll
            for (int p = 0; p < 32; p++) acc[p] = fmaf(xs[l][pbase + p], bn, acc[p]);
        }
    }
    size_t base = (size_t)blockIdx.x * (HEADDIM * D_STATE);
    #pragma unroll
    for (int p = 0; p < 32; p++) g_states[base + (size_t)(pbase + p) * 64 + n] = acc[p];
}

// ---------------- sequential inter-chunk scan (per b,h) ----------------------
__global__ void __launch_bounds__(256) chunkscan_k() {
    int h = blockIdx.x & 15, b = blockIdx.x >> 4;
    float s[32];
    #pragma unroll
    for (int k = 0; k < 32; k++) s[k] = 0.f;
    for (int c = 0; c < NCHUNK; c++) {
        int bc = b * NCHUNK + c;
        size_t base = (size_t)(bc * NHEADS + h) * (HEADDIM * D_STATE);
        float dec = __expf(g_cum[(bc * CHUNKL + CHUNKL - 1) * NHEADS + h]);
        #pragma unroll
        for (int k = 0; k < 32; k++) {
            size_t idx = base + threadIdx.x + k * 256;
            g_prev[idx] = s[k];
            s[k] = s[k] * dec + g_states[idx];
        }
    }
}

// ---------------- y = intra + inter + D*x ------------------------------------
__global__ void __launch_bounds__(256) y_k(const float* __restrict__ Dv) {
    int h = blockIdx.x & 15, bc = blockIdx.x >> 4;
    int i0 = blockIdx.y * 64;
    int t0 = bc * CHUNKL;
    int il = threadIdx.x & 63;
    int pg = threadIdx.x >> 6;
    int pbase = pg * 32;
    int i = i0 + il;
    int ti = t0 + i;
    float cum_i = g_cum[ti * NHEADS + h];
    float acc[32];
    #pragma unroll
    for (int p = 0; p < 32; p++) acc[p] = 0.f;
    __shared__ float xs[32][132];
    __shared__ float att[64][33];
    __shared__ float cj[32];
    __shared__ float dtj[32];
    const float* sc_base = g_scores + (size_t)bc * 65536 + (size_t)i * 256;

    // intra-chunk: sum_{j<=i} scores[i,j]*exp(cum_i-cum_j)*dt_j * x[j,:]
    for (int j0 = 0; j0 < i0 + 64; j0 += 32) {
        __syncthreads();
        for (int idx = threadIdx.x; idx < 32 * 128; idx += 256) {
            int r = idx >> 7, p = idx & 127;
            xs[r][p] = g_xbc[(size_t)(t0 + j0 + r) * CONV_DIM + h * HEADDIM + p];
        }
        if (threadIdx.x < 32) {
            int tt = t0 + j0 + threadIdx.x;
            cj[threadIdx.x]  = g_cum[tt * NHEADS + h];
            dtj[threadIdx.x] = g_dt[tt * NHEADS + h];
        }
        __syncthreads();
        #pragma unroll
        for (int q = 0; q < 8; q++) {
            int jl = pg * 8 + q;
            int j = j0 + jl;
            float a = 0.f;
            if (j <= i) a = sc_base[j] * __expf(cum_i - cj[jl]) * dtj[jl];
            att[il][jl] = a;
        }
        __syncthreads();
        #pragma unroll 4
        for (int jl = 0; jl < 32; jl++) {
            float a = att[il][jl];
            #pragma unroll
            for (int p = 0; p < 32; p++) acc[p] = fmaf(a, xs[jl][pbase + p], acc[p]);
        }
    }

    // inter-chunk: += exp(cum_i) * sum_n C[i,n] * prev[h,p,n]
    float ei = __expf(cum_i);
    float (*prevs)[132] = xs;                         // reuse (16 rows used)
    float (*Ci)[17] = (float (*)[17]) & att[0][0];    // 64x17 fits in att
    size_t pv_base = (size_t)(bc * NHEADS + h) * (HEADDIM * D_STATE);
    for (int n0 = 0; n0 < 64; n0 += 16) {
        __syncthreads();
        for (int idx = threadIdx.x; idx < 16 * 128; idx += 256) {
            int nn = idx & 15, p = idx >> 4;
            prevs[nn][p] = g_prev[pv_base + (size_t)p * 64 + n0 + nn];
        }
        for (int idx = threadIdx.x; idx < 64 * 16; idx += 256) {
            int r = idx >> 4, nn = idx & 15;
            Ci[r][nn] = g_xbc[(size_t)(t0 + i0 + r) * CONV_DIM + D_INNER + D_STATE + n0 + nn];
        }
        __syncthreads();
        #pragma unroll
        for (int nn = 0; nn < 16; nn++) {
            float cv = Ci[il][nn] * ei;
            #pragma unroll
            for (int p = 0; p < 32; p++) acc[p] = fmaf(cv, prevs[nn][pbase + p], acc[p]);
        }
    }

    float Dh = Dv[h];
    float* yout = g_y + (size_t)ti * D_INNER + h * HEADDIM + pbase;
    const float* xrow = g_xbc + (size_t)ti * CONV_DIM + h * HEADDIM + pbase;
    #pragma unroll
    for (int p = 0; p < 32; p++) yout[p] = acc[p] + Dh * xrow[p];
}

// ---------------- gating + rmsnorm (in place on g_y, tf32-rounded) -----------
__global__ void __launch_bounds__(256) gate_rms_k(const float* __restrict__ rms_w) {
    int t = blockIdx.x;
    float v[8]; float ss = 0.f, dummy = 0.f;
    const float* yrow = g_y + (size_t)t * D_INNER;
    const float* zrow = g_zx + (size_t)t * D_IN_PROJ;
    #pragma unroll
    for (int k = 0; k < 8; k++) {
        int idx = threadIdx.x + k * 256;
        float z = zrow[idx];
        float gv = yrow[idx] * (z / (1.f + __expf(-z)));
        v[k] = gv; ss += gv * gv;
    }
    block_reduce2(ss, dummy);
    float scale = rsqrtf(ss * (1.f / D_INNER) + 1e-5f);
    float* grow = g_y + (size_t)t * D_INNER;
    #pragma unroll
    for (int k = 0; k < 8; k++) {
        int idx = threadIdx.x + k * 256;
        grow[idx] = to_tf32(v[k] * scale * rms_w[idx]);
    }
}

// ---------------- host launch -------------------------------------------------
extern "C" void kernel_launch(void* const* d_in, const int* in_sizes, int n_in,
                              void* d_out, int out_size) {
    (void)in_sizes; (void)n_in; (void)out_size;
    const float* u        = (const float*)d_in[0];
    const float* in_proj  = (const float*)d_in[1];
    const float* conv_w   = (const float*)d_in[2];
    const float* conv_b   = (const float*)d_in[3];
    const float* dt_bias  = (const float*)d_in[4];
    const float* A_log    = (const float*)d_in[5];
    const float* Dv       = (const float*)d_in[6];
    const float* xnw      = (const float*)d_in[7];
    const float* xnb      = (const float*)d_in[8];
    const float* rms_w    = (const float*)d_in[9];
    const float* out_proj = (const float*)d_in[10];
    float* out = (float*)d_out;

    void *p_w1n, *p_w2n, *p_uln, *p_zx, *p_y;
    cudaGetSymbolAddress(&p_w1n, g_w1n);
    cudaGetSymbolAddress(&p_w2n, g_w2n);
    cudaGetSymbolAddress(&p_uln, g_uln);
    cudaGetSymbolAddress(&p_zx,  g_zx);
    cudaGetSymbolAddress(&p_y,   g_y);

    static int smem_set = 0;
    if (!smem_set) {
        cudaFuncSetAttribute(gemm_tf32_nt,
                             cudaFuncAttributeMaxDynamicSharedMemorySize, GEMM_SMEM);
        smem_set = 1;
    }

    l2norm_rows_k<<<D_IN_PROJ, 256>>>(in_proj, (float*)p_w1n, DIMX, 0.03125f); // fold DIM^-0.5
    l2norm_rows_k<<<DIMX, 256>>>(out_proj, (float*)p_w2n, D_INNER, 1.0f);
    layernorm_k<<<NT, 256>>>(u, xnw, xnb);

    gemm_tf32_nt<<<dim3((D_IN_PROJ + 127) / 128, NT / 256), 512, GEMM_SMEM>>>(
        (const float*)p_uln, (const float*)p_w1n, (float*)p_zx, NT, D_IN_PROJ, DIMX);

    dtcum_k<<<NBC * NHEADS, 256>>>(dt_bias, A_log);
    conv_silu_k<<<dim3(NT, (CONV_DIM + 255) / 256), 256>>>(conv_w, conv_b);
    scores_k<<<dim3(NBC, 8), 256>>>();
    states_k<<<NBC * NHEADS, 256>>>();
    chunkscan_k<<<BATCHN * NHEADS, 256>>>();
    y_k<<<dim3(NBC * NHEADS, 4), 256>>>(Dv);
    gate_rms_k<<<NT, 256>>>(rms_w);

    gemm_tf32_nt<<<dim3(DIMX / 128, NT / 256), 512, GEMM_SMEM>>>(
        (const float*)p_y, (const float*)p_w2n, out, NT, DIMX, D_INNER);
}

// round 8
// speedup vs baseline: 1.5945x; 1.5945x over previous
#include <cuda_runtime.h>
#include <cstdint>

#define DIMX      1024
#define D_INNER   2048
#define NHEADS    16
#define HEADDIM   128
#define D_STATE   64
#define CONV_DIM  2176      // D_INNER + 2*D_STATE
#define D_IN_PROJ 4240      // 2*D_INNER + 2*D_STATE + NHEADS
#define CHUNKL    256
#define NCHUNK    16        // per batch (4096/256)
#define BATCHN    2
#define SEQLENN   4096
#define NT        8192      // BATCH*SEQLEN tokens
#define NBC       32        // BATCH*NCHUNK

// ---------------- scratch (static device memory; no runtime allocation) ----
__device__ float g_w1n[(size_t)D_IN_PROJ * DIMX];        // normalized in_proj (scale folded, tf32-rounded)
__device__ float g_w2n[(size_t)DIMX * D_INNER];          // normalized out_proj (tf32-rounded)
__device__ float g_uln[(size_t)NT * DIMX];               // layernormed input (tf32-rounded)
__device__ float g_zx [(size_t)NT * D_IN_PROJ];          // zxbcdt
__device__ float g_xbc[(size_t)NT * CONV_DIM];           // conv+silu output
__device__ float g_dt [(size_t)NT * NHEADS];
__device__ float g_cum[(size_t)NT * NHEADS];             // in-chunk inclusive cumsum of dt*A
__device__ float g_scores[(size_t)NBC * CHUNKL * CHUNKL];
__device__ float g_states[(size_t)NBC * NHEADS * HEADDIM * D_STATE];
__device__ float g_prev  [(size_t)NBC * NHEADS * HEADDIM * D_STATE];
__device__ float g_y  [(size_t)NT * D_INNER];            // y, then g (in place, tf32-rounded)

// ---------------- helpers ---------------------------------------------------
__device__ __forceinline__ float to_tf32(float x) {
    float r;
    asm("cvt.rna.tf32.f32 %0, %1;" : "=f"(r) : "f"(x));
    return r;
}

__device__ __forceinline__ void cp_async16(void* smem_dst, const void* gmem_src, int src_sz) {
    uint32_t s = (uint32_t)__cvta_generic_to_shared(smem_dst);
    asm volatile("cp.async.cg.shared.global [%0], [%1], 16, %2;"
                 :: "r"(s), "l"(gmem_src), "r"(src_sz));
}
__device__ __forceinline__ void cp_commit() { asm volatile("cp.async.commit_group;"); }
template <int N> __device__ __forceinline__ void cp_wait() {
    asm volatile("cp.async.wait_group %0;" :: "n"(N));
}

__device__ __forceinline__ uint32_t smem_u32(const void* p) {
    return (uint32_t)__cvta_generic_to_shared(p);
}

__device__ __forceinline__ void ldsm4(uint32_t* r, uint32_t addr) {
    asm volatile("ldmatrix.sync.aligned.m8n8.x4.shared.b16 {%0,%1,%2,%3}, [%4];"
                 : "=r"(r[0]), "=r"(r[1]), "=r"(r[2]), "=r"(r[3]) : "r"(addr));
}

__device__ __forceinline__ void mma_tf32(float* c, const uint32_t* a,
                                         uint32_t b0, uint32_t b1) {
    asm volatile("mma.sync.aligned.m16n8k8.row.col.f32.tf32.tf32.f32 "
                 "{%0,%1,%2,%3}, {%4,%5,%6,%7}, {%8,%9}, {%0,%1,%2,%3};"
                 : "+f"(c[0]), "+f"(c[1]), "+f"(c[2]), "+f"(c[3])
                 : "r"(a[0]), "r"(a[1]), "r"(a[2]), "r"(a[3]), "r"(b0), "r"(b1));
}

__device__ __forceinline__ void block_reduce2(float& a, float& b) {
    __shared__ float sa[32], sb[32];
    int lane = threadIdx.x & 31, w = threadIdx.x >> 5;
    #pragma unroll
    for (int o = 16; o; o >>= 1) {
        a += __shfl_down_sync(0xffffffffu, a, o);
        b += __shfl_down_sync(0xffffffffu, b, o);
    }
    if (lane == 0) { sa[w] = a; sb[w] = b; }
    __syncthreads();
    if (w == 0) {
        int nw = blockDim.x >> 5;
        a = (lane < nw) ? sa[lane] : 0.f;
        b = (lane < nw) ? sb[lane] : 0.f;
        #pragma unroll
        for (int o = 16; o; o >>= 1) {
            a += __shfl_down_sync(0xffffffffu, a, o);
            b += __shfl_down_sync(0xffffffffu, b, o);
        }
        if (lane == 0) { sa[0] = a; sb[0] = b; }
    }
    __syncthreads();
    a = sa[0]; b = sb[0];
}

// ---------------- weight l2-normalization (tf32-rounded output) -------------
__global__ void __launch_bounds__(256) l2norm_rows_k(const float* __restrict__ W,
                                                     float* __restrict__ out,
                                                     int K, float extra) {
    int row = blockIdx.x;
    const float* src = W + (size_t)row * K;
    float ss = 0.f, dummy = 0.f;
    for (int i = threadIdx.x; i < K; i += blockDim.x) { float v = src[i]; ss += v * v; }
    block_reduce2(ss, dummy);
    float scale = extra / fmaxf(sqrtf(ss), 1e-6f);
    float* dst = out + (size_t)row * K;
    for (int i = threadIdx.x; i < K; i += blockDim.x) dst[i] = to_tf32(src[i] * scale);
}

// ---------------- input layernorm (tf32-rounded output) ---------------------
__global__ void __launch_bounds__(256) layernorm_k(const float* __restrict__ u,
                                                   const float* __restrict__ w,
                                                   const float* __restrict__ b) {
    int t = blockIdx.x;
    const float* x = u + (size_t)t * DIMX;
    float v[4]; float s = 0.f, s2 = 0.f;
    #pragma unroll
    for (int k = 0; k < 4; k++) {
        v[k] = x[threadIdx.x + k * 256];
        s += v[k]; s2 += v[k] * v[k];
    }
    block_reduce2(s, s2);
    float mu = s * (1.f / DIMX);
    float var = s2 * (1.f / DIMX) - mu * mu;
    float inv = rsqrtf(var + 1e-5f);
    float* o = g_uln + (size_t)t * DIMX;
    #pragma unroll
    for (int k = 0; k < 4; k++) {
        int i = threadIdx.x + k * 256;
        o[i] = to_tf32((v[k] - mu) * inv * w[i] + b[i]);
    }
}

// ---------------- tf32 GEMM: C[M,N] = A[M,K] * B[N,K]^T ----------------------
// 256x128 block tile, BK=32, 4-stage cp.async pipeline, 8 warps (4x2),
// warp tile 64x64. ldmatrix.x4 fragment loads + mma.m16n8k8.tf32.
#define GSTAGES 4
#define ASF (256 * 36)
#define BSF (128 * 36)
#define STAGE_F (ASF + BSF)
#define GEMM_SMEM (GSTAGES * STAGE_F * 4)

__device__ __forceinline__ void gemm_load_stage(float* stage,
                                                const float* __restrict__ A,
                                                const float* __restrict__ B,
                                                int bm, int bn, int k0,
                                                int N, int K, int tid) {
    float* As = stage;
    float* Bs = stage + ASF;
    #pragma unroll
    for (int u = 0; u < 8; u++) {           // A: 256x32 = 2048 float4
        int idx = tid + u * 256;
        int r = idx >> 3, cc = (idx & 7) * 4;
        cp_async16(&As[r * 36 + cc], A + (size_t)(bm + r) * K + k0 + cc, 16);
    }
    #pragma unroll
    for (int u = 0; u < 4; u++) {           // B: 128x32 = 1024 float4
        int idx = tid + u * 256;
        int r = idx >> 3, cc = (idx & 7) * 4;
        int brow = bn + r;
        int safe = (brow < N) ? brow : (N - 1);
        cp_async16(&Bs[r * 36 + cc], B + (size_t)safe * K + k0 + cc, (brow < N) ? 16 : 0);
    }
    cp_commit();
}

__global__ void __launch_bounds__(256, 1) gemm_tf32_nt(const float* __restrict__ A,
                                                       const float* __restrict__ B,
                                                       float* __restrict__ C,
                                                       int M, int N, int K) {
    extern __shared__ float sm[];
    int bm = blockIdx.y * 256;
    int bn = blockIdx.x * 128;
    int tid = threadIdx.x;
    int warp = tid >> 5;
    int lane = tid & 31;
    int wm = (warp >> 1) * 64;
    int wn = (warp & 1) * 64;

    // ldmatrix lane-address components
    int a_row = lane & 15;                   // row within 16-row block
    int a_ko  = (lane >> 4) * 4;             // k offset 0 / 4
    int b_n   = (lane & 7) + ((lane & 16) >> 1);  // n within 16-col block
    int b_ko  = ((lane >> 3) & 1) * 4;       // k offset 0 / 4

    float c[4][8][4];                        // [m-block][n-block8][regs]
    #pragma unroll
    for (int i = 0; i < 4; i++)
        #pragma unroll
        for (int j = 0; j < 8; j++)
            #pragma unroll
            for (int r = 0; r < 4; r++) c[i][j][r] = 0.f;

    int kTiles = K >> 5;
    #pragma unroll
    for (int s = 0; s < GSTAGES - 1; s++)
        gemm_load_stage(sm + s * STAGE_F, A, B, bm, bn, s * 32, N, K, tid);

    for (int kt = 0; kt < kTiles; kt++) {
        cp_wait<GSTAGES - 2>();
        __syncthreads();
        int nk = kt + GSTAGES - 1;
        if (nk < kTiles)
            gemm_load_stage(sm + (nk % GSTAGES) * STAGE_F, A, B, bm, bn,
                            nk * 32, N, K, tid);

        const float* As = sm + (kt % GSTAGES) * STAGE_F;
        const float* Bs = As + ASF;
        #pragma unroll
        for (int ks = 0; ks < 32; ks += 8) {
            uint32_t a[4][4];
            #pragma unroll
            for (int i = 0; i < 4; i++)
                ldsm4(a[i], smem_u32(&As[(wm + i * 16 + a_row) * 36 + ks + a_ko]));
            #pragma unroll
            for (int jb = 0; jb < 4; jb++) {
                uint32_t b[4];
                ldsm4(b, smem_u32(&Bs[(wn + jb * 16 + b_n) * 36 + ks + b_ko]));
                #pragma unroll
                for (int i = 0; i < 4; i++) {
                    mma_tf32(c[i][2 * jb],     a[i], b[0], b[1]);
                    mma_tf32(c[i][2 * jb + 1], a[i], b[2], b[3]);
                }
            }
        }
    }
    __syncthreads();

    // epilogue: thread holds rows (t/4, t/4+8), cols 2*(t%4)+{0,1} per 16x8 tile
    int t4 = lane >> 2;
    int t2 = (lane & 3) * 2;
    #pragma unroll
    for (int i = 0; i < 4; i++) {
        #pragma unroll
        for (int j = 0; j < 8; j++) {
            int col = bn + wn + j * 8 + t2;
            if (col < N) {
                size_t r0 = (size_t)(bm + wm + i * 16 + t4) * N + col;
                size_t r1 = r0 + (size_t)8 * N;
                *(float2*)&C[r0] = make_float2(c[i][j][0], c[i][j][1]);
                *(float2*)&C[r1] = make_float2(c[i][j][2], c[i][j][3]);
            }
        }
    }
}

// ---------------- dt = softplus(raw + bias); cum = cumsum(dt*A) per chunk ----
__global__ void __launch_bounds__(256) dtcum_k(const float* __restrict__ dt_bias,
                                               const float* __restrict__ A_log) {
    int h = blockIdx.x & 15, bc = blockIdx.x >> 4;
    int t = bc * CHUNKL + threadIdx.x;
    float raw = g_zx[(size_t)t * D_IN_PROJ + (D_INNER + CONV_DIM) + h] + dt_bias[h];
    float dt = (raw > 20.f) ? raw : log1pf(expf(raw));
    g_dt[t * NHEADS + h] = dt;
    float dA = dt * (-expf(A_log[h]));
    __shared__ float sc[CHUNKL];
    sc[threadIdx.x] = dA;
    __syncthreads();
    for (int off = 1; off < CHUNKL; off <<= 1) {
        float add = (threadIdx.x >= off) ? sc[threadIdx.x - off] : 0.f;
        __syncthreads();
        sc[threadIdx.x] += add;
        __syncthreads();
    }
    g_cum[t * NHEADS + h] = sc[threadIdx.x];
}

// ---------------- causal depthwise conv (w=4) + SiLU -------------------------
__global__ void __launch_bounds__(256) conv_silu_k(const float* __restrict__ cw,
                                                   const float* __restrict__ cb) {
    int t = blockIdx.x;
    int ch = blockIdx.y * 256 + threadIdx.x;
    if (ch >= CONV_DIM) return;
    int l = t & (SEQLENN - 1);
    float acc = cb[ch];
    #pragma unroll
    for (int j = 0; j < 4; j++) {
        int ll = l - 3 + j;
        if (ll >= 0)
            acc = fmaf(cw[ch * 4 + j], g_zx[(size_t)(t - 3 + j) * D_IN_PROJ + D_INNER + ch], acc);
    }
    float sv = acc / (1.f + __expf(-acc));
    g_xbc[(size_t)t * CONV_DIM + ch] = sv;
}

// ---------------- scores[i,j] = C_i . B_j (lower triangle tiles only) --------
__global__ void __launch_bounds__(256) scores_k() {
    int bc = blockIdx.x;
    int i0 = blockIdx.y * 32;
    int t0 = bc * CHUNKL;
    __shared__ float Cs[32][65];
    __shared__ float Bs[64][65];
    for (int idx = threadIdx.x; idx < 32 * 64; idx += 256) {
        int r = idx >> 6, n = idx & 63;
        Cs[r][n] = g_xbc[(size_t)(t0 + i0 + r) * CONV_DIM + D_INNER + D_STATE + n];
    }
    for (int j0 = 0; j0 <= i0 + 31; j0 += 64) {
        __syncthreads();
        for (int idx = threadIdx.x; idx < 64 * 64; idx += 256) {
            int r = idx >> 6, n = idx & 63;
            Bs[r][n] = g_xbc[(size_t)(t0 + j0 + r) * CONV_DIM + D_INNER + n];
        }
        __syncthreads();
        #pragma unroll
        for (int q = 0; q < 8; q++) {
            int o = threadIdx.x + q * 256;
            int ii = o >> 6, jj = o & 63;
            float acc = 0.f;
            #pragma unroll
            for (int n = 0; n < 64; n++) acc = fmaf(Cs[ii][n], Bs[jj][n], acc);
            g_scores[(size_t)bc * 65536 + (size_t)(i0 + ii) * 256 + (j0 + jj)] = acc;
        }
    }
}

// ---------------- chunk-end states: state[p,n] = sum_l x[l,p]*dt*decay*B[l,n]-
__global__ void __launch_bounds__(256) states_k() {
    int h = blockIdx.x & 15, bc = blockIdx.x >> 4;
    int t0 = bc * CHUNKL;
    float cum_last = g_cum[(t0 + CHUNKL - 1) * NHEADS + h];
    int n = threadIdx.x & 63;
    int pbase = (threadIdx.x >> 6) * 32;
    float acc[32];
    #pragma unroll
    for (int p = 0; p < 32; p++) acc[p] = 0.f;
    __shared__ float xs[32][128];
    __shared__ float Bs[32][65];
    __shared__ float coef[32];
    for (int l0 = 0; l0 < CHUNKL; l0 += 32) {
        __syncthreads();
        for (int idx = threadIdx.x; idx < 32 * 128; idx += 256) {
            int r = idx >> 7, p = idx & 127;
            xs[r][p] = g_xbc[(size_t)(t0 + l0 + r) * CONV_DIM + h * HEADDIM + p];
        }
        for (int idx = threadIdx.x; idx < 32 * 64; idx += 256) {
            int r = idx >> 6, nn = idx & 63;
            Bs[r][nn] = g_xbc[(size_t)(t0 + l0 + r) * CONV_DIM + D_INNER + nn];
        }
        if (threadIdx.x < 32) {
            int tt = t0 + l0 + threadIdx.x;
            coef[threadIdx.x] = g_dt[tt * NHEADS + h] * __expf(cum_last - g_cum[tt * NHEADS + h]);
        }
        __syncthreads();
        #pragma unroll 4
        for (int l = 0; l < 32; l++) {
            float bn = Bs[l][n] * coef[l];
            #pragma unroll
            for (int p = 0; p < 32; p++) acc[p] = fmaf(xs[l][pbase + p], bn, acc[p]);
        }
    }
    size_t base = (size_t)blockIdx.x * (HEADDIM * D_STATE);
    #pragma unroll
    for (int p = 0; p < 32; p++) g_states[base + (size_t)(pbase + p) * 64 + n] = acc[p];
}

// ---------------- sequential inter-chunk scan (per b,h) ----------------------
__global__ void __launch_bounds__(256) chunkscan_k() {
    int h = blockIdx.x & 15, b = blockIdx.x >> 4;
    float s[32];
    #pragma unroll
    for (int k = 0; k < 32; k++) s[k] = 0.f;
    for (int c = 0; c < NCHUNK; c++) {
        int bc = b * NCHUNK + c;
        size_t base = (size_t)(bc * NHEADS + h) * (HEADDIM * D_STATE);
        float dec = __expf(g_cum[(bc * CHUNKL + CHUNKL - 1) * NHEADS + h]);
        #pragma unroll
        for (int k = 0; k < 32; k++) {
            size_t idx = base + threadIdx.x + k * 256;
            g_prev[idx] = s[k];
            s[k] = s[k] * dec + g_states[idx];
        }
    }
}

// ---------------- y = intra + inter + D*x ------------------------------------
__global__ void __launch_bounds__(256) y_k(const float* __restrict__ Dv) {
    int h = blockIdx.x & 15, bc = blockIdx.x >> 4;
    int i0 = blockIdx.y * 64;
    int t0 = bc * CHUNKL;
    int il = threadIdx.x & 63;
    int pg = threadIdx.x >> 6;
    int pbase = pg * 32;
    int i = i0 + il;
    int ti = t0 + i;
    float cum_i = g_cum[ti * NHEADS + h];
    float acc[32];
    #pragma unroll
    for (int p = 0; p < 32; p++) acc[p] = 0.f;
    __shared__ float xs[32][132];
    __shared__ float att[64][33];
    __shared__ float cj[32];
    __shared__ float dtj[32];
    const float* sc_base = g_scores + (size_t)bc * 65536 + (size_t)i * 256;

    // intra-chunk: sum_{j<=i} scores[i,j]*exp(cum_i-cum_j)*dt_j * x[j,:]
    for (int j0 = 0; j0 < i0 + 64; j0 += 32) {
        __syncthreads();
        for (int idx = threadIdx.x; idx < 32 * 128; idx += 256) {
            int r = idx >> 7, p = idx & 127;
            xs[r][p] = g_xbc[(size_t)(t0 + j0 + r) * CONV_DIM + h * HEADDIM + p];
        }
        if (threadIdx.x < 32) {
            int tt = t0 + j0 + threadIdx.x;
            cj[threadIdx.x]  = g_cum[tt * NHEADS + h];
            dtj[threadIdx.x] = g_dt[tt * NHEADS + h];
        }
        __syncthreads();
        #pragma unroll
        for (int q = 0; q < 8; q++) {
            int jl = pg * 8 + q;
            int j = j0 + jl;
            float a = 0.f;
            if (j <= i) a = sc_base[j] * __expf(cum_i - cj[jl]) * dtj[jl];
            att[il][jl] = a;
        }
        __syncthreads();
        #pragma unroll 4
        for (int jl = 0; jl < 32; jl++) {
            float a = att[il][jl];
            #pragma unroll
            for (int p = 0; p < 32; p++) acc[p] = fmaf(a, xs[jl][pbase + p], acc[p]);
        }
    }

    // inter-chunk: += exp(cum_i) * sum_n C[i,n] * prev[h,p,n]
    float ei = __expf(cum_i);
    float (*prevs)[132] = xs;                         // reuse (16 rows used)
    float (*Ci)[17] = (float (*)[17]) & att[0][0];    // 64x17 fits in att
    size_t pv_base = (size_t)(bc * NHEADS + h) * (HEADDIM * D_STATE);
    for (int n0 = 0; n0 < 64; n0 += 16) {
        __syncthreads();
        for (int idx = threadIdx.x; idx < 16 * 128; idx += 256) {
            int nn = idx & 15, p = idx >> 4;
            prevs[nn][p] = g_prev[pv_base + (size_t)p * 64 + n0 + nn];
        }
        for (int idx = threadIdx.x; idx < 64 * 16; idx += 256) {
            int r = idx >> 4, nn = idx & 15;
            Ci[r][nn] = g_xbc[(size_t)(t0 + i0 + r) * CONV_DIM + D_INNER + D_STATE + n0 + nn];
        }
        __syncthreads();
        #pragma unroll
        for (int nn = 0; nn < 16; nn++) {
            float cv = Ci[il][nn] * ei;
            #pragma unroll
            for (int p = 0; p < 32; p++) acc[p] = fmaf(cv, prevs[nn][pbase + p], acc[p]);
        }
    }

    float Dh = Dv[h];
    float* yout = g_y + (size_t)ti * D_INNER + h * HEADDIM + pbase;
    const float* xrow = g_xbc + (size_t)ti * CONV_DIM + h * HEADDIM + pbase;
    #pragma unroll
    for (int p = 0; p < 32; p++) yout[p] = acc[p] + Dh * xrow[p];
}

// ---------------- gating + rmsnorm (in place on g_y, tf32-rounded) -----------
__global__ void __launch_bounds__(256) gate_rms_k(const float* __restrict__ rms_w) {
    int t = blockIdx.x;
    float v[8]; float ss = 0.f, dummy = 0.f;
    const float* yrow = g_y + (size_t)t * D_INNER;
    const float* zrow = g_zx + (size_t)t * D_IN_PROJ;
    #pragma unroll
    for (int k = 0; k < 8; k++) {
        int idx = threadIdx.x + k * 256;
        float z = zrow[idx];
        float gv = yrow[idx] * (z / (1.f + __expf(-z)));
        v[k] = gv; ss += gv * gv;
    }
    block_reduce2(ss, dummy);
    float scale = rsqrtf(ss * (1.f / D_INNER) + 1e-5f);
    float* grow = g_y + (size_t)t * D_INNER;
    #pragma unroll
    for (int k = 0; k < 8; k++) {
        int idx = threadIdx.x + k * 256;
        grow[idx] = to_tf32(v[k] * scale * rms_w[idx]);
    }
}

// ---------------- host launch -------------------------------------------------
extern "C" void kernel_launch(void* const* d_in, const int* in_sizes, int n_in,
                              void* d_out, int out_size) {
    (void)in_sizes; (void)n_in; (void)out_size;
    const float* u        = (const float*)d_in[0];
    const float* in_proj  = (const float*)d_in[1];
    const float* conv_w   = (const float*)d_in[2];
    const float* conv_b   = (const float*)d_in[3];
    const float* dt_bias  = (const float*)d_in[4];
    const float* A_log    = (const float*)d_in[5];
    const float* Dv       = (const float*)d_in[6];
    const float* xnw      = (const float*)d_in[7];
    const float* xnb      = (const float*)d_in[8];
    const float* rms_w    = (const float*)d_in[9];
    const float* out_proj = (const float*)d_in[10];
    float* out = (float*)d_out;

    void *p_w1n, *p_w2n, *p_uln, *p_zx, *p_y;
    cudaGetSymbolAddress(&p_w1n, g_w1n);
    cudaGetSymbolAddress(&p_w2n, g_w2n);
    cudaGetSymbolAddress(&p_uln, g_uln);
    cudaGetSymbolAddress(&p_zx,  g_zx);
    cudaGetSymbolAddress(&p_y,   g_y);

    static int smem_set = 0;
    if (!smem_set) {
        cudaFuncSetAttribute(gemm_tf32_nt,
                             cudaFuncAttributeMaxDynamicSharedMemorySize, GEMM_SMEM);
        smem_set = 1;
    }

    l2norm_rows_k<<<D_IN_PROJ, 256>>>(in_proj, (float*)p_w1n, DIMX, 0.03125f); // fold DIM^-0.5
    l2norm_rows_k<<<DIMX, 256>>>(out_proj, (float*)p_w2n, D_INNER, 1.0f);
    layernorm_k<<<NT, 256>>>(u, xnw, xnb);

    gemm_tf32_nt<<<dim3((D_IN_PROJ + 127) / 128, NT / 256), 256, GEMM_SMEM>>>(
        (const float*)p_uln, (const float*)p_w1n, (float*)p_zx, NT, D_IN_PROJ, DIMX);

    dtcum_k<<<NBC * NHEADS, 256>>>(dt_bias, A_log);
    conv_silu_k<<<dim3(NT, (CONV_DIM + 255) / 256), 256>>>(conv_w, conv_b);
    scores_k<<<dim3(NBC, 8), 256>>>();
    states_k<<<NBC * NHEADS, 256>>>();
    chunkscan_k<<<BATCHN * NHEADS, 256>>>();
    y_k<<<dim3(NBC * NHEADS, 4), 256>>>(Dv);
    gate_rms_k<<<NT, 256>>>(rms_w);

    gemm_tf32_nt<<<dim3(DIMX / 128, NT / 256), 256, GEMM_SMEM>>>(
        (const float*)p_y, (const float*)p_w2n, out, NT, DIMX, D_INNER);
}

// round 11
// speedup vs baseline: 1.7003x; 1.0663x over previous
#include <cuda_runtime.h>
#include <cstdint>

#define DIMX      1024
#define D_INNER   2048
#define NHEADS    16
#define HEADDIM   128
#define D_STATE   64
#define CONV_DIM  2176      // D_INNER + 2*D_STATE
#define D_IN_PROJ 4240      // 2*D_INNER + 2*D_STATE + NHEADS
#define CHUNKL    256
#define NCHUNK    16        // per batch (4096/256)
#define BATCHN    2
#define SEQLENN   4096
#define NT        8192      // BATCH*SEQLEN tokens
#define NBC       32        // BATCH*NCHUNK

// ---------------- scratch (static device memory; no runtime allocation) ----
__device__ float g_w1n[(size_t)D_IN_PROJ * DIMX];        // normalized in_proj (scale folded, tf32-rounded)
__device__ float g_w2n[(size_t)DIMX * D_INNER];          // normalized out_proj (tf32-rounded)
__device__ float g_uln[(size_t)NT * DIMX];               // layernormed input (tf32-rounded)
__device__ float g_zx [(size_t)NT * D_IN_PROJ];          // zxbcdt
__device__ float g_xbc[(size_t)NT * CONV_DIM];           // conv+silu output
__device__ float g_dt [(size_t)NT * NHEADS];
__device__ float g_cum[(size_t)NT * NHEADS];             // in-chunk inclusive cumsum of dt*A
__device__ float g_scores[(size_t)NBC * CHUNKL * CHUNKL];
__device__ float g_states[(size_t)NBC * NHEADS * HEADDIM * D_STATE];
__device__ float g_prev  [(size_t)NBC * NHEADS * HEADDIM * D_STATE];
__device__ float g_y  [(size_t)NT * D_INNER];            // y, then g (in place, tf32-rounded)

// ---------------- helpers ---------------------------------------------------
__device__ __forceinline__ float to_tf32(float x) {
    float r;
    asm("cvt.rna.tf32.f32 %0, %1;" : "=f"(r) : "f"(x));
    return r;
}

__device__ __forceinline__ void cp_async16(void* smem_dst, const void* gmem_src, int src_sz) {
    uint32_t s = (uint32_t)__cvta_generic_to_shared(smem_dst);
    asm volatile("cp.async.cg.shared.global [%0], [%1], 16, %2;"
                 :: "r"(s), "l"(gmem_src), "r"(src_sz));
}
__device__ __forceinline__ void cp_commit() { asm volatile("cp.async.commit_group;"); }
template <int N> __device__ __forceinline__ void cp_wait() {
    asm volatile("cp.async.wait_group %0;" :: "n"(N));
}

__device__ __forceinline__ uint32_t smem_u32(const void* p) {
    return (uint32_t)__cvta_generic_to_shared(p);
}

__device__ __forceinline__ void ldsm4(uint32_t* r, uint32_t addr) {
    asm volatile("ldmatrix.sync.aligned.m8n8.x4.shared.b16 {%0,%1,%2,%3}, [%4];"
                 : "=r"(r[0]), "=r"(r[1]), "=r"(r[2]), "=r"(r[3]) : "r"(addr));
}

__device__ __forceinline__ void mma_tf32(float* c, const uint32_t* a,
                                         uint32_t b0, uint32_t b1) {
    asm volatile("mma.sync.aligned.m16n8k8.row.col.f32.tf32.tf32.f32 "
                 "{%0,%1,%2,%3}, {%4,%5,%6,%7}, {%8,%9}, {%0,%1,%2,%3};"
                 : "+f"(c[0]), "+f"(c[1]), "+f"(c[2]), "+f"(c[3])
                 : "r"(a[0]), "r"(a[1]), "r"(a[2]), "r"(a[3]), "r"(b0), "r"(b1));
}

__device__ __forceinline__ void block_reduce2(float& a, float& b) {
    __shared__ float sa[32], sb[32];
    int lane = threadIdx.x & 31, w = threadIdx.x >> 5;
    #pragma unroll
    for (int o = 16; o; o >>= 1) {
        a += __shfl_down_sync(0xffffffffu, a, o);
        b += __shfl_down_sync(0xffffffffu, b, o);
    }
    if (lane == 0) { sa[w] = a; sb[w] = b; }
    __syncthreads();
    if (w == 0) {
        int nw = blockDim.x >> 5;
        a = (lane < nw) ? sa[lane] : 0.f;
        b = (lane < nw) ? sb[lane] : 0.f;
        #pragma unroll
        for (int o = 16; o; o >>= 1) {
            a += __shfl_down_sync(0xffffffffu, a, o);
            b += __shfl_down_sync(0xffffffffu, b, o);
        }
        if (lane == 0) { sa[0] = a; sb[0] = b; }
    }
    __syncthreads();
    a = sa[0]; b = sb[0];
}

// ---------------- weight l2-normalization (tf32-rounded output) -------------
__global__ void __launch_bounds__(256) l2norm_rows_k(const float* __restrict__ W,
                                                     float* __restrict__ out,
                                                     int K, float extra) {
    int row = blockIdx.x;
    const float* src = W + (size_t)row * K;
    float ss = 0.f, dummy = 0.f;
    for (int i = threadIdx.x; i < K; i += blockDim.x) { float v = src[i]; ss += v * v; }
    block_reduce2(ss, dummy);
    float scale = extra / fmaxf(sqrtf(ss), 1e-6f);
    float* dst = out + (size_t)row * K;
    for (int i = threadIdx.x; i < K; i += blockDim.x) dst[i] = to_tf32(src[i] * scale);
}

// ---------------- input layernorm (tf32-rounded output) ---------------------
__global__ void __launch_bounds__(256) layernorm_k(const float* __restrict__ u,
                                                   const float* __restrict__ w,
                                                   const float* __restrict__ b) {
    int t = blockIdx.x;
    const float* x = u + (size_t)t * DIMX;
    float v[4]; float s = 0.f, s2 = 0.f;
    #pragma unroll
    for (int k = 0; k < 4; k++) {
        v[k] = x[threadIdx.x + k * 256];
        s += v[k]; s2 += v[k] * v[k];
    }
    block_reduce2(s, s2);
    float mu = s * (1.f / DIMX);
    float var = s2 * (1.f / DIMX) - mu * mu;
    float inv = rsqrtf(var + 1e-5f);
    float* o = g_uln + (size_t)t * DIMX;
    #pragma unroll
    for (int k = 0; k < 4; k++) {
        int i = threadIdx.x + k * 256;
        o[i] = to_tf32((v[k] - mu) * inv * w[i] + b[i]);
    }
}

// ---------------- tf32 GEMM: C[M,N] = A[M,K] * B[N,K]^T ----------------------
// 128x128 block tile, BK=32, 3-stage cp.async pipeline, 8 warps (2x4),
// warp tile 64x32, ldmatrix.x4 + mma.m16n8k8.tf32. 2 CTAs/SM.
#define GSTAGES 3
#define ASF (128 * 36)
#define BSF (128 * 36)
#define STAGE_F (ASF + BSF)
#define GEMM_SMEM (GSTAGES * STAGE_F * 4)

__device__ __forceinline__ void gemm_load_stage(float* stage,
                                                const float* __restrict__ A,
                                                const float* __restrict__ B,
                                                int bm, int bn, int k0,
                                                int N, int K, int tid) {
    float* As = stage;
    float* Bs = stage + ASF;
    #pragma unroll
    for (int u = 0; u < 4; u++) {           // A: 128x32 = 1024 float4
        int idx = tid + u * 256;
        int r = idx >> 3, cc = (idx & 7) * 4;
        cp_async16(&As[r * 36 + cc], A + (size_t)(bm + r) * K + k0 + cc, 16);
    }
    #pragma unroll
    for (int u = 0; u < 4; u++) {           // B: 128x32 = 1024 float4
        int idx = tid + u * 256;
        int r = idx >> 3, cc = (idx & 7) * 4;
        int brow = bn + r;
        int safe = (brow < N) ? brow : (N - 1);
        cp_async16(&Bs[r * 36 + cc], B + (size_t)safe * K + k0 + cc, (brow < N) ? 16 : 0);
    }
    cp_commit();
}

__global__ void __launch_bounds__(256, 2) gemm_tf32_nt(const float* __restrict__ A,
                                                       const float* __restrict__ B,
                                                       float* __restrict__ C,
                                                       int M, int N, int K) {
    extern __shared__ float sm[];
    int bm = blockIdx.y * 128;
    int bn = blockIdx.x * 128;
    int tid = threadIdx.x;
    int warp = tid >> 5;
    int lane = tid & 31;
    int wm = (warp >> 2) * 64;               // 2 m-groups of 64
    int wn = (warp & 3) * 32;                // 4 n-groups of 32

    // ldmatrix lane-address components
    int a_row = lane & 15;
    int a_ko  = (lane >> 4) * 4;
    int b_n   = (lane & 7) + ((lane & 16) >> 1);
    int b_ko  = ((lane >> 3) & 1) * 4;

    float c[4][4][4];                        // [m16-block][n8-block][regs]
    #pragma unroll
    for (int i = 0; i < 4; i++)
        #pragma unroll
        for (int j = 0; j < 4; j++)
            #pragma unroll
            for (int r = 0; r < 4; r++) c[i][j][r] = 0.f;

    int kTiles = K >> 5;
    #pragma unroll
    for (int s = 0; s < GSTAGES - 1; s++)
        gemm_load_stage(sm + s * STAGE_F, A, B, bm, bn, s * 32, N, K, tid);

    for (int kt = 0; kt < kTiles; kt++) {
        cp_wait<GSTAGES - 2>();
        __syncthreads();
        int nk = kt + GSTAGES - 1;
        if (nk < kTiles)
            gemm_load_stage(sm + (nk % GSTAGES) * STAGE_F, A, B, bm, bn,
                            nk * 32, N, K, tid);

        const float* As = sm + (kt % GSTAGES) * STAGE_F;
        const float* Bs = As + ASF;
        #pragma unroll
        for (int ks = 0; ks < 32; ks += 8) {
            uint32_t a[4][4];
            #pragma unroll
            for (int i = 0; i < 4; i++)
                ldsm4(a[i], smem_u32(&As[(wm + i * 16 + a_row) * 36 + ks + a_ko]));
            #pragma unroll
            for (int jb = 0; jb < 2; jb++) {
                uint32_t b[4];
                ldsm4(b, smem_u32(&Bs[(wn + jb * 16 + b_n) * 36 + ks + b_ko]));
                #pragma unroll
                for (int i = 0; i < 4; i++) {
                    mma_tf32(c[i][2 * jb],     a[i], b[0], b[1]);
                    mma_tf32(c[i][2 * jb + 1], a[i], b[2], b[3]);
                }
            }
        }
    }
    __syncthreads();

    // epilogue: thread holds rows (t/4, t/4+8), cols 2*(t%4)+{0,1} per 16x8 tile
    int t4 = lane >> 2;
    int t2 = (lane & 3) * 2;
    #pragma unroll
    for (int i = 0; i < 4; i++) {
        #pragma unroll
        for (int j = 0; j < 4; j++) {
            int col = bn + wn + j * 8 + t2;
            if (col < N) {
                size_t r0 = (size_t)(bm + wm + i * 16 + t4) * N + col;
                size_t r1 = r0 + (size_t)8 * N;
                *(float2*)&C[r0] = make_float2(c[i][j][0], c[i][j][1]);
                *(float2*)&C[r1] = make_float2(c[i][j][2], c[i][j][3]);
            }
        }
    }
}

// ---------------- dt = softplus(raw + bias); cum = cumsum(dt*A) per chunk ----
__global__ void __launch_bounds__(256) dtcum_k(const float* __restrict__ dt_bias,
                                               const float* __restrict__ A_log) {
    int h = blockIdx.x & 15, bc = blockIdx.x >> 4;
    int t = bc * CHUNKL + threadIdx.x;
    float raw = g_zx[(size_t)t * D_IN_PROJ + (D_INNER + CONV_DIM) + h] + dt_bias[h];
    float dt = (raw > 20.f) ? raw : log1pf(expf(raw));
    g_dt[t * NHEADS + h] = dt;
    float dA = dt * (-expf(A_log[h]));
    __shared__ float sc[CHUNKL];
    sc[threadIdx.x] = dA;
    __syncthreads();
    for (int off = 1; off < CHUNKL; off <<= 1) {
        float add = (threadIdx.x >= off) ? sc[threadIdx.x - off] : 0.f;
        __syncthreads();
        sc[threadIdx.x] += add;
        __syncthreads();
    }
    g_cum[t * NHEADS + h] = sc[threadIdx.x];
}

// ---------------- causal depthwise conv (w=4) + SiLU -------------------------
__global__ void __launch_bounds__(256) conv_silu_k(const float* __restrict__ cw,
                                                   const float* __restrict__ cb) {
    int t = blockIdx.x;
    int ch = blockIdx.y * 256 + threadIdx.x;
    if (ch >= CONV_DIM) return;
    int l = t & (SEQLENN - 1);
    float acc = cb[ch];
    #pragma unroll
    for (int j = 0; j < 4; j++) {
        int ll = l - 3 + j;
        if (ll >= 0)
            acc = fmaf(cw[ch * 4 + j], g_zx[(size_t)(t - 3 + j) * D_IN_PROJ + D_INNER + ch], acc);
    }
    float sv = acc / (1.f + __expf(-acc));
    g_xbc[(size_t)t * CONV_DIM + ch] = sv;
}

// ---------------- scores[i,j] = C_i . B_j (lower triangle tiles only) --------
__global__ void __launch_bounds__(256) scores_k() {
    int bc = blockIdx.x;
    int i0 = blockIdx.y * 32;
    int t0 = bc * CHUNKL;
    __shared__ float Cs[32][65];
    __shared__ float Bs[64][65];
    for (int idx = threadIdx.x; idx < 32 * 64; idx += 256) {
        int r = idx >> 6, n = idx & 63;
        Cs[r][n] = g_xbc[(size_t)(t0 + i0 + r) * CONV_DIM + D_INNER + D_STATE + n];
    }
    for (int j0 = 0; j0 <= i0 + 31; j0 += 64) {
        __syncthreads();
        for (int idx = threadIdx.x; idx < 64 * 64; idx += 256) {
            int r = idx >> 6, n = idx & 63;
            Bs[r][n] = g_xbc[(size_t)(t0 + j0 + r) * CONV_DIM + D_INNER + n];
        }
        __syncthreads();
        #pragma unroll
        for (int q = 0; q < 8; q++) {
            int o = threadIdx.x + q * 256;
            int ii = o >> 6, jj = o & 63;
            float acc = 0.f;
            #pragma unroll
            for (int n = 0; n < 64; n++) acc = fmaf(Cs[ii][n], Bs[jj][n], acc);
            g_scores[(size_t)bc * 65536 + (size_t)(i0 + ii) * 256 + (j0 + jj)] = acc;
        }
    }
}

// ---------------- chunk-end states: state[p,n] = sum_l x[l,p]*dt*decay*B[l,n]-
__global__ void __launch_bounds__(256) states_k() {
    int h = blockIdx.x & 15, bc = blockIdx.x >> 4;
    int t0 = bc * CHUNKL;
    float cum_last = g_cum[(t0 + CHUNKL - 1) * NHEADS + h];
    int n = threadIdx.x & 63;
    int pbase = (threadIdx.x >> 6) * 32;
    float acc[32];
    #pragma unroll
    for (int p = 0; p < 32; p++) acc[p] = 0.f;
    __shared__ float xs[32][128];
    __shared__ float Bs[32][65];
    __shared__ float coef[32];
    for (int l0 = 0; l0 < CHUNKL; l0 += 32) {
        __syncthreads();
        for (int idx = threadIdx.x; idx < 32 * 128; idx += 256) {
            int r = idx >> 7, p = idx & 127;
            xs[r][p] = g_xbc[(size_t)(t0 + l0 + r) * CONV_DIM + h * HEADDIM + p];
        }
        for (int idx = threadIdx.x; idx < 32 * 64; idx += 256) {
            int r = idx >> 6, nn = idx & 63;
            Bs[r][nn] = g_xbc[(size_t)(t0 + l0 + r) * CONV_DIM + D_INNER + nn];
        }
        if (threadIdx.x < 32) {
            int tt = t0 + l0 + threadIdx.x;
            coef[threadIdx.x] = g_dt[tt * NHEADS + h] * __expf(cum_last - g_cum[tt * NHEADS + h]);
        }
        __syncthreads();
        #pragma unroll 4
        for (int l = 0; l < 32; l++) {
            float bn = Bs[l][n] * coef[l];
            #pragma unroll
            for (int p = 0; p < 32; p++) acc[p] = fmaf(xs[l][pbase + p], bn, acc[p]);
        }
    }
    size_t base = (size_t)blockIdx.x * (HEADDIM * D_STATE);
    #pragma unroll
    for (int p = 0; p < 32; p++) g_states[base + (size_t)(pbase + p) * 64 + n] = acc[p];
}

// ---------------- sequential inter-chunk scan (per b,h) ----------------------
__global__ void __launch_bounds__(256) chunkscan_k() {
    int h = blockIdx.x & 15, b = blockIdx.x >> 4;
    float s[32];
    #pragma unroll
    for (int k = 0; k < 32; k++) s[k] = 0.f;
    for (int c = 0; c < NCHUNK; c++) {
        int bc = b * NCHUNK + c;
        size_t base = (size_t)(bc * NHEADS + h) * (HEADDIM * D_STATE);
        float dec = __expf(g_cum[(bc * CHUNKL + CHUNKL - 1) * NHEADS + h]);
        #pragma unroll
        for (int k = 0; k < 32; k++) {
            size_t idx = base + threadIdx.x + k * 256;
            g_prev[idx] = s[k];
            s[k] = s[k] * dec + g_states[idx];
        }
    }
}

// ---------------- y = intra + inter + D*x ------------------------------------
__global__ void __launch_bounds__(256) y_k(const float* __restrict__ Dv) {
    int h = blockIdx.x & 15, bc = blockIdx.x >> 4;
    int i0 = blockIdx.y * 64;
    int t0 = bc * CHUNKL;
    int il = threadIdx.x & 63;
    int pg = threadIdx.x >> 6;
    int pbase = pg * 32;
    int i = i0 + il;
    int ti = t0 + i;
    float cum_i = g_cum[ti * NHEADS + h];
    float acc[32];
    #pragma unroll
    for (int p = 0; p < 32; p++) acc[p] = 0.f;
    __shared__ float xs[32][132];
    __shared__ float att[64][33];
    __shared__ float cj[32];
    __shared__ float dtj[32];
    const float* sc_base = g_scores + (size_t)bc * 65536 + (size_t)i * 256;

    // intra-chunk: sum_{j<=i} scores[i,j]*exp(cum_i-cum_j)*dt_j * x[j,:]
    for (int j0 = 0; j0 < i0 + 64; j0 += 32) {
        __syncthreads();
        for (int idx = threadIdx.x; idx < 32 * 128; idx += 256) {
            int r = idx >> 7, p = idx & 127;
            xs[r][p] = g_xbc[(size_t)(t0 + j0 + r) * CONV_DIM + h * HEADDIM + p];
        }
        if (threadIdx.x < 32) {
            int tt = t0 + j0 + threadIdx.x;
            cj[threadIdx.x]  = g_cum[tt * NHEADS + h];
            dtj[threadIdx.x] = g_dt[tt * NHEADS + h];
        }
        __syncthreads();
        #pragma unroll
        for (int q = 0; q < 8; q++) {
            int jl = pg * 8 + q;
            int j = j0 + jl;
            float a = 0.f;
            if (j <= i) a = sc_base[j] * __expf(cum_i - cj[jl]) * dtj[jl];
            att[il][jl] = a;
        }
        __syncthreads();
        #pragma unroll 4
        for (int jl = 0; jl < 32; jl++) {
            float a = att[il][jl];
            #pragma unroll
            for (int p = 0; p < 32; p++) acc[p] = fmaf(a, xs[jl][pbase + p], acc[p]);
        }
    }

    // inter-chunk: += exp(cum_i) * sum_n C[i,n] * prev[h,p,n]
    float ei = __expf(cum_i);
    float (*prevs)[132] = xs;                         // reuse (16 rows used)
    float (*Ci)[17] = (float (*)[17]) & att[0][0];    // 64x17 fits in att
    size_t pv_base = (size_t)(bc * NHEADS + h) * (HEADDIM * D_STATE);
    for (int n0 = 0; n0 < 64; n0 += 16) {
        __syncthreads();
        for (int idx = threadIdx.x; idx < 16 * 128; idx += 256) {
            int nn = idx & 15, p = idx >> 4;
            prevs[nn][p] = g_prev[pv_base + (size_t)p * 64 + n0 + nn];
        }
        for (int idx = threadIdx.x; idx < 64 * 16; idx += 256) {
            int r = idx >> 4, nn = idx & 15;
            Ci[r][nn] = g_xbc[(size_t)(t0 + i0 + r) * CONV_DIM + D_INNER + D_STATE + n0 + nn];
        }
        __syncthreads();
        #pragma unroll
        for (int nn = 0; nn < 16; nn++) {
            float cv = Ci[il][nn] * ei;
            #pragma unroll
            for (int p = 0; p < 32; p++) acc[p] = fmaf(cv, prevs[nn][pbase + p], acc[p]);
        }
    }

    float Dh = Dv[h];
    float* yout = g_y + (size_t)ti * D_INNER + h * HEADDIM + pbase;
    const float* xrow = g_xbc + (size_t)ti * CONV_DIM + h * HEADDIM + pbase;
    #pragma unroll
    for (int p = 0; p < 32; p++) yout[p] = acc[p] + Dh * xrow[p];
}

// ---------------- gating + rmsnorm (in place on g_y, tf32-rounded) -----------
__global__ void __launch_bounds__(256) gate_rms_k(const float* __restrict__ rms_w) {
    int t = blockIdx.x;
    float v[8]; float ss = 0.f, dummy = 0.f;
    const float* yrow = g_y + (size_t)t * D_INNER;
    const float* zrow = g_zx + (size_t)t * D_IN_PROJ;
    #pragma unroll
    for (int k = 0; k < 8; k++) {
        int idx = threadIdx.x + k * 256;
        float z = zrow[idx];
        float gv = yrow[idx] * (z / (1.f + __expf(-z)));
        v[k] = gv; ss += gv * gv;
    }
    block_reduce2(ss, dummy);
    float scale = rsqrtf(ss * (1.f / D_INNER) + 1e-5f);
    float* grow = g_y + (size_t)t * D_INNER;
    #pragma unroll
    for (int k = 0; k < 8; k++) {
        int idx = threadIdx.x + k * 256;
        grow[idx] = to_tf32(v[k] * scale * rms_w[idx]);
    }
}

// ---------------- host launch -------------------------------------------------
extern "C" void kernel_launch(void* const* d_in, const int* in_sizes, int n_in,
                              void* d_out, int out_size) {
    (void)in_sizes; (void)n_in; (void)out_size;
    const float* u        = (const float*)d_in[0];
    const float* in_proj  = (const float*)d_in[1];
    const float* conv_w   = (const float*)d_in[2];
    const float* conv_b   = (const float*)d_in[3];
    const float* dt_bias  = (const float*)d_in[4];
    const float* A_log    = (const float*)d_in[5];
    const float* Dv       = (const float*)d_in[6];
    const float* xnw      = (const float*)d_in[7];
    const float* xnb      = (const float*)d_in[8];
    const float* rms_w    = (const float*)d_in[9];
    const float* out_proj = (const float*)d_in[10];
    float* out = (float*)d_out;

    void *p_w1n, *p_w2n, *p_uln, *p_zx, *p_y;
    cudaGetSymbolAddress(&p_w1n, g_w1n);
    cudaGetSymbolAddress(&p_w2n, g_w2n);
    cudaGetSymbolAddress(&p_uln, g_uln);
    cudaGetSymbolAddress(&p_zx,  g_zx);
    cudaGetSymbolAddress(&p_y,   g_y);

    static int smem_set = 0;
    if (!smem_set) {
        cudaFuncSetAttribute(gemm_tf32_nt,
                             cudaFuncAttributeMaxDynamicSharedMemorySize, GEMM_SMEM);
        smem_set = 1;
    }

    l2norm_rows_k<<<D_IN_PROJ, 256>>>(in_proj, (float*)p_w1n, DIMX, 0.03125f); // fold DIM^-0.5
    l2norm_rows_k<<<DIMX, 256>>>(out_proj, (float*)p_w2n, D_INNER, 1.0f);
    layernorm_k<<<NT, 256>>>(u, xnw, xnb);

    gemm_tf32_nt<<<dim3((D_IN_PROJ + 127) / 128, NT / 128), 256, GEMM_SMEM>>>(
        (const float*)p_uln, (const float*)p_w1n, (float*)p_zx, NT, D_IN_PROJ, DIMX);

    dtcum_k<<<NBC * NHEADS, 256>>>(dt_bias, A_log);
    conv_silu_k<<<dim3(NT, (CONV_DIM + 255) / 256), 256>>>(conv_w, conv_b);
    scores_k<<<dim3(NBC, 8), 256>>>();
    states_k<<<NBC * NHEADS, 256>>>();
    chunkscan_k<<<BATCHN * NHEADS, 256>>>();
    y_k<<<dim3(NBC * NHEADS, 4), 256>>>(Dv);
    gate_rms_k<<<NT, 256>>>(rms_w);

    gemm_tf32_nt<<<dim3(DIMX / 128, NT / 128), 256, GEMM_SMEM>>>(
        (const float*)p_y, (const float*)p_w2n, out, NT, DIMX, D_INNER);
}

// round 12
// speedup vs baseline: 1.7027x; 1.0014x over previous
#include <cuda_runtime.h>
#include <cstdint>

#define DIMX      1024
#define D_INNER   2048
#define NHEADS    16
#define HEADDIM   128
#define D_STATE   64
#define CONV_DIM  2176      // D_INNER + 2*D_STATE
#define D_IN_PROJ 4240      // 2*D_INNER + 2*D_STATE + NHEADS
#define CHUNKL    256
#define NCHUNK    16        // per batch (4096/256)
#define BATCHN    2
#define SEQLENN   4096
#define NT        8192      // BATCH*SEQLEN tokens
#define NBC       32        // BATCH*NCHUNK

// ---------------- scratch (static device memory; no runtime allocation) ----
__device__ float g_w1n[(size_t)D_IN_PROJ * DIMX];        // normalized in_proj (scale folded, tf32-rounded)
__device__ float g_w2n[(size_t)DIMX * D_INNER];          // normalized out_proj (tf32-rounded)
__device__ float g_uln[(size_t)NT * DIMX];               // layernormed input (tf32-rounded)
__device__ float g_zx [(size_t)NT * D_IN_PROJ];          // zxbcdt
__device__ float g_xbc[(size_t)NT * CONV_DIM];           // conv+silu output
__device__ float g_dt [(size_t)NT * NHEADS];
__device__ float g_cum[(size_t)NT * NHEADS];             // in-chunk inclusive cumsum of dt*A
__device__ float g_scores[(size_t)NBC * CHUNKL * CHUNKL];
__device__ float g_states[(size_t)NBC * NHEADS * HEADDIM * D_STATE];
__device__ float g_prev  [(size_t)NBC * NHEADS * HEADDIM * D_STATE];
__device__ float g_y  [(size_t)NT * D_INNER];            // y, then g (in place, tf32-rounded)

// ---------------- helpers ---------------------------------------------------
__device__ __forceinline__ float to_tf32(float x) {
    float r;
    asm("cvt.rna.tf32.f32 %0, %1;" : "=f"(r) : "f"(x));
    return r;
}

__device__ __forceinline__ void cp_async16(void* smem_dst, const void* gmem_src, int src_sz) {
    uint32_t s = (uint32_t)__cvta_generic_to_shared(smem_dst);
    asm volatile("cp.async.cg.shared.global [%0], [%1], 16, %2;"
                 :: "r"(s), "l"(gmem_src), "r"(src_sz));
}
__device__ __forceinline__ void cp_commit() { asm volatile("cp.async.commit_group;"); }
template <int N> __device__ __forceinline__ void cp_wait() {
    asm volatile("cp.async.wait_group %0;" :: "n"(N));
}

__device__ __forceinline__ uint32_t smem_u32(const void* p) {
    return (uint32_t)__cvta_generic_to_shared(p);
}

__device__ __forceinline__ void ldsm4(uint32_t* r, uint32_t addr) {
    asm volatile("ldmatrix.sync.aligned.m8n8.x4.shared.b16 {%0,%1,%2,%3}, [%4];"
                 : "=r"(r[0]), "=r"(r[1]), "=r"(r[2]), "=r"(r[3]) : "r"(addr));
}

__device__ __forceinline__ void mma_tf32(float* c, const uint32_t* a,
                                         uint32_t b0, uint32_t b1) {
    asm volatile("mma.sync.aligned.m16n8k8.row.col.f32.tf32.tf32.f32 "
                 "{%0,%1,%2,%3}, {%4,%5,%6,%7}, {%8,%9}, {%0,%1,%2,%3};"
                 : "+f"(c[0]), "+f"(c[1]), "+f"(c[2]), "+f"(c[3])
                 : "r"(a[0]), "r"(a[1]), "r"(a[2]), "r"(a[3]), "r"(b0), "r"(b1));
}

__device__ __forceinline__ void block_reduce2(float& a, float& b) {
    __shared__ float sa[32], sb[32];
    int lane = threadIdx.x & 31, w = threadIdx.x >> 5;
    #pragma unroll
    for (int o = 16; o; o >>= 1) {
        a += __shfl_down_sync(0xffffffffu, a, o);
        b += __shfl_down_sync(0xffffffffu, b, o);
    }
    if (lane == 0) { sa[w] = a; sb[w] = b; }
    __syncthreads();
    if (w == 0) {
        int nw = blockDim.x >> 5;
        a = (lane < nw) ? sa[lane] : 0.f;
        b = (lane < nw) ? sb[lane] : 0.f;
        #pragma unroll
        for (int o = 16; o; o >>= 1) {
            a += __shfl_down_sync(0xffffffffu, a, o);
            b += __shfl_down_sync(0xffffffffu, b, o);
        }
        if (lane == 0) { sa[0] = a; sb[0] = b; }
    }
    __syncthreads();
    a = sa[0]; b = sb[0];
}

// ---------------- weight l2-normalization (tf32-rounded output) -------------
__global__ void __launch_bounds__(256) l2norm_rows_k(const float* __restrict__ W,
                                                     float* __restrict__ out,
                                                     int K, float extra) {
    int row = blockIdx.x;
    const float* src = W + (size_t)row * K;
    float ss = 0.f, dummy = 0.f;
    for (int i = threadIdx.x; i < K; i += blockDim.x) { float v = src[i]; ss += v * v; }
    block_reduce2(ss, dummy);
    float scale = extra / fmaxf(sqrtf(ss), 1e-6f);
    float* dst = out + (size_t)row * K;
    for (int i = threadIdx.x; i < K; i += blockDim.x) dst[i] = to_tf32(src[i] * scale);
}

// ---------------- input layernorm (tf32-rounded output) ---------------------
__global__ void __launch_bounds__(256) layernorm_k(const float* __restrict__ u,
                                                   const float* __restrict__ w,
                                                   const float* __restrict__ b) {
    int t = blockIdx.x;
    const float* x = u + (size_t)t * DIMX;
    float v[4]; float s = 0.f, s2 = 0.f;
    #pragma unroll
    for (int k = 0; k < 4; k++) {
        v[k] = x[threadIdx.x + k * 256];
        s += v[k]; s2 += v[k] * v[k];
    }
    block_reduce2(s, s2);
    float mu = s * (1.f / DIMX);
    float var = s2 * (1.f / DIMX) - mu * mu;
    float inv = rsqrtf(var + 1e-5f);
    float* o = g_uln + (size_t)t * DIMX;
    #pragma unroll
    for (int k = 0; k < 4; k++) {
        int i = threadIdx.x + k * 256;
        o[i] = to_tf32((v[k] - mu) * inv * w[i] + b[i]);
    }
}

// ---------------- tf32 GEMM: C[M,N] = A[M,K] * B[N,K]^T ----------------------
// 128x128 block tile, BK=32, 3-stage cp.async pipeline, 8 warps (2x4),
// warp tile 64x32, ldmatrix.x4 + mma.m16n8k8.tf32. 2 CTAs/SM.
#define GSTAGES 3
#define ASF (128 * 36)
#define BSF (128 * 36)
#define STAGE_F (ASF + BSF)
#define GEMM_SMEM (GSTAGES * STAGE_F * 4)

__device__ __forceinline__ void gemm_load_stage(float* stage,
                                                const float* __restrict__ A,
                                                const float* __restrict__ B,
                                                int bm, int bn, int k0,
                                                int N, int K, int tid) {
    float* As = stage;
    float* Bs = stage + ASF;
    #pragma unroll
    for (int u = 0; u < 4; u++) {           // A: 128x32 = 1024 float4
        int idx = tid + u * 256;
        int r = idx >> 3, cc = (idx & 7) * 4;
        cp_async16(&As[r * 36 + cc], A + (size_t)(bm + r) * K + k0 + cc, 16);
    }
    #pragma unroll
    for (int u = 0; u < 4; u++) {           // B: 128x32 = 1024 float4
        int idx = tid + u * 256;
        int r = idx >> 3, cc = (idx & 7) * 4;
        int brow = bn + r;
        int safe = (brow < N) ? brow : (N - 1);
        cp_async16(&Bs[r * 36 + cc], B + (size_t)safe * K + k0 + cc, (brow < N) ? 16 : 0);
    }
    cp_commit();
}

__global__ void __launch_bounds__(256, 2) gemm_tf32_nt(const float* __restrict__ A,
                                                       const float* __restrict__ B,
                                                       float* __restrict__ C,
                                                       int M, int N, int K) {
    extern __shared__ float sm[];
    int bm = blockIdx.y * 128;
    int bn = blockIdx.x * 128;
    int tid = threadIdx.x;
    int warp = tid >> 5;
    int lane = tid & 31;
    int wm = (warp >> 2) * 64;               // 2 m-groups of 64
    int wn = (warp & 3) * 32;                // 4 n-groups of 32

    // ldmatrix lane-address components
    int a_row = lane & 15;
    int a_ko  = (lane >> 4) * 4;
    int b_n   = (lane & 7) + ((lane & 16) >> 1);
    int b_ko  = ((lane >> 3) & 1) * 4;

    float c[4][4][4];                        // [m16-block][n8-block][regs]
    #pragma unroll
    for (int i = 0; i < 4; i++)
        #pragma unroll
        for (int j = 0; j < 4; j++)
            #pragma unroll
            for (int r = 0; r < 4; r++) c[i][j][r] = 0.f;

    int kTiles = K >> 5;
    #pragma unroll
    for (int s = 0; s < GSTAGES - 1; s++)
        gemm_load_stage(sm + s * STAGE_F, A, B, bm, bn, s * 32, N, K, tid);

    for (int kt = 0; kt < kTiles; kt++) {
        cp_wait<GSTAGES - 2>();
        __syncthreads();
        int nk = kt + GSTAGES - 1;
        if (nk < kTiles)
            gemm_load_stage(sm + (nk % GSTAGES) * STAGE_F, A, B, bm, bn,
                            nk * 32, N, K, tid);

        const float* As = sm + (kt % GSTAGES) * STAGE_F;
        const float* Bs = As + ASF;
        #pragma unroll
        for (int ks = 0; ks < 32; ks += 8) {
            uint32_t a[4][4];
            #pragma unroll
            for (int i = 0; i < 4; i++)
                ldsm4(a[i], smem_u32(&As[(wm + i * 16 + a_row) * 36 + ks + a_ko]));
            #pragma unroll
            for (int jb = 0; jb < 2; jb++) {
                uint32_t b[4];
                ldsm4(b, smem_u32(&Bs[(wn + jb * 16 + b_n) * 36 + ks + b_ko]));
                #pragma unroll
                for (int i = 0; i < 4; i++) {
                    mma_tf32(c[i][2 * jb],     a[i], b[0], b[1]);
                    mma_tf32(c[i][2 * jb + 1], a[i], b[2], b[3]);
                }
            }
        }
    }
    __syncthreads();

    // epilogue: thread holds rows (t/4, t/4+8), cols 2*(t%4)+{0,1} per 16x8 tile
    int t4 = lane >> 2;
    int t2 = (lane & 3) * 2;
    #pragma unroll
    for (int i = 0; i < 4; i++) {
        #pragma unroll
        for (int j = 0; j < 4; j++) {
            int col = bn + wn + j * 8 + t2;
            if (col < N) {
                size_t r0 = (size_t)(bm + wm + i * 16 + t4) * N + col;
                size_t r1 = r0 + (size_t)8 * N;
                *(float2*)&C[r0] = make_float2(c[i][j][0], c[i][j][1]);
                *(float2*)&C[r1] = make_float2(c[i][j][2], c[i][j][3]);
            }
        }
    }
}

// ---------------- dt = softplus(raw + bias); cum = cumsum(dt*A) per chunk ----
__global__ void __launch_bounds__(256) dtcum_k(const float* __restrict__ dt_bias,
                                               const float* __restrict__ A_log) {
    int h = blockIdx.x & 15, bc = blockIdx.x >> 4;
    int t = bc * CHUNKL + threadIdx.x;
    float raw = g_zx[(size_t)t * D_IN_PROJ + (D_INNER + CONV_DIM) + h] + dt_bias[h];
    float dt = (raw > 20.f) ? raw : log1pf(expf(raw));
    g_dt[t * NHEADS + h] = dt;
    float dA = dt * (-expf(A_log[h]));
    __shared__ float sc[CHUNKL];
    sc[threadIdx.x] = dA;
    __syncthreads();
    for (int off = 1; off < CHUNKL; off <<= 1) {
        float add = (threadIdx.x >= off) ? sc[threadIdx.x - off] : 0.f;
        __syncthreads();
        sc[threadIdx.x] += add;
        __syncthreads();
    }
    g_cum[t * NHEADS + h] = sc[threadIdx.x];
}

// ---------------- causal depthwise conv (w=4) + SiLU -------------------------
__global__ void __launch_bounds__(256) conv_silu_k(const float* __restrict__ cw,
                                                   const float* __restrict__ cb) {
    int t = blockIdx.x;
    int ch = blockIdx.y * 256 + threadIdx.x;
    if (ch >= CONV_DIM) return;
    int l = t & (SEQLENN - 1);
    float acc = cb[ch];
    #pragma unroll
    for (int j = 0; j < 4; j++) {
        int ll = l - 3 + j;
        if (ll >= 0)
            acc = fmaf(cw[ch * 4 + j], g_zx[(size_t)(t - 3 + j) * D_IN_PROJ + D_INNER + ch], acc);
    }
    float sv = acc / (1.f + __expf(-acc));
    g_xbc[(size_t)t * CONV_DIM + ch] = sv;
}

// ---------------- scores[i,j] = C_i . B_j (lower triangle tiles only) --------
__global__ void __launch_bounds__(256) scores_k() {
    int bc = blockIdx.x;
    int i0 = blockIdx.y * 32;
    int t0 = bc * CHUNKL;
    __shared__ float Cs[32][65];
    __shared__ float Bs[64][65];
    for (int idx = threadIdx.x; idx < 32 * 64; idx += 256) {
        int r = idx >> 6, n = idx & 63;
        Cs[r][n] = g_xbc[(size_t)(t0 + i0 + r) * CONV_DIM + D_INNER + D_STATE + n];
    }
    for (int j0 = 0; j0 <= i0 + 31; j0 += 64) {
        __syncthreads();
        for (int idx = threadIdx.x; idx < 64 * 64; idx += 256) {
            int r = idx >> 6, n = idx & 63;
            Bs[r][n] = g_xbc[(size_t)(t0 + j0 + r) * CONV_DIM + D_INNER + n];
        }
        __syncthreads();
        #pragma unroll
        for (int q = 0; q < 8; q++) {
            int o = threadIdx.x + q * 256;
            int ii = o >> 6, jj = o & 63;
            float acc = 0.f;
            #pragma unroll
            for (int n = 0; n < 64; n++) acc = fmaf(Cs[ii][n], Bs[jj][n], acc);
            g_scores[(size_t)bc * 65536 + (size_t)(i0 + ii) * 256 + (j0 + jj)] = acc;
        }
    }
}

// ---------------- chunk-end states: state[p,n] = sum_l x[l,p]*dt*decay*B[l,n]-
__global__ void __launch_bounds__(256) states_k() {
    int h = blockIdx.x & 15, bc = blockIdx.x >> 4;
    int t0 = bc * CHUNKL;
    float cum_last = g_cum[(t0 + CHUNKL - 1) * NHEADS + h];
    int n = threadIdx.x & 63;
    int pbase = (threadIdx.x >> 6) * 32;
    float acc[32];
    #pragma unroll
    for (int p = 0; p < 32; p++) acc[p] = 0.f;
    __shared__ float xs[32][128];
    __shared__ float Bs[32][65];
    __shared__ float coef[32];
    for (int l0 = 0; l0 < CHUNKL; l0 += 32) {
        __syncthreads();
        for (int idx = threadIdx.x; idx < 32 * 128; idx += 256) {
            int r = idx >> 7, p = idx & 127;
            xs[r][p] = g_xbc[(size_t)(t0 + l0 + r) * CONV_DIM + h * HEADDIM + p];
        }
        for (int idx = threadIdx.x; idx < 32 * 64; idx += 256) {
            int r = idx >> 6, nn = idx & 63;
            Bs[r][nn] = g_xbc[(size_t)(t0 + l0 + r) * CONV_DIM + D_INNER + nn];
        }
        if (threadIdx.x < 32) {
            int tt = t0 + l0 + threadIdx.x;
            coef[threadIdx.x] = g_dt[tt * NHEADS + h] * __expf(cum_last - g_cum[tt * NHEADS + h]);
        }
        __syncthreads();
        #pragma unroll 4
        for (int l = 0; l < 32; l++) {
            float bn = Bs[l][n] * coef[l];
            #pragma unroll
            for (int p = 0; p < 32; p++) acc[p] = fmaf(xs[l][pbase + p], bn, acc[p]);
        }
    }
    size_t base = (size_t)blockIdx.x * (HEADDIM * D_STATE);
    #pragma unroll
    for (int p = 0; p < 32; p++) g_states[base + (size_t)(pbase + p) * 64 + n] = acc[p];
}

// ---------------- sequential inter-chunk scan (per b,h) ----------------------
__global__ void __launch_bounds__(256) chunkscan_k() {
    int h = blockIdx.x & 15, b = blockIdx.x >> 4;
    float s[32];
    #pragma unroll
    for (int k = 0; k < 32; k++) s[k] = 0.f;
    for (int c = 0; c < NCHUNK; c++) {
        int bc = b * NCHUNK + c;
        size_t base = (size_t)(bc * NHEADS + h) * (HEADDIM * D_STATE);
        float dec = __expf(g_cum[(bc * CHUNKL + CHUNKL - 1) * NHEADS + h]);
        #pragma unroll
        for (int k = 0; k < 32; k++) {
            size_t idx = base + threadIdx.x + k * 256;
            g_prev[idx] = s[k];
            s[k] = s[k] * dec + g_states[idx];
        }
    }
}

// ---------------- y = intra + inter + D*x ------------------------------------
__global__ void __launch_bounds__(256) y_k(const float* __restrict__ Dv) {
    int h = blockIdx.x & 15, bc = blockIdx.x >> 4;
    int i0 = blockIdx.y * 64;
    int t0 = bc * CHUNKL;
    int il = threadIdx.x & 63;
    int pg = threadIdx.x >> 6;
    int pbase = pg * 32;
    int i = i0 + il;
    int ti = t0 + i;
    float cum_i = g_cum[ti * NHEADS + h];
    float acc[32];
    #pragma unroll
    for (int p = 0; p < 32; p++) acc[p] = 0.f;
    __shared__ float xs[32][132];
    __shared__ float att[64][33];
    __shared__ float cj[32];
    __shared__ float dtj[32];
    const float* sc_base = g_scores + (size_t)bc * 65536 + (size_t)i * 256;

    // intra-chunk: sum_{j<=i} scores[i,j]*exp(cum_i-cum_j)*dt_j * x[j,:]
    for (int j0 = 0; j0 < i0 + 64; j0 += 32) {
        __syncthreads();
        for (int idx = threadIdx.x; idx < 32 * 128; idx += 256) {
            int r = idx >> 7, p = idx & 127;
            xs[r][p] = g_xbc[(size_t)(t0 + j0 + r) * CONV_DIM + h * HEADDIM + p];
        }
        if (threadIdx.x < 32) {
            int tt = t0 + j0 + threadIdx.x;
            cj[threadIdx.x]  = g_cum[tt * NHEADS + h];
            dtj[threadIdx.x] = g_dt[tt * NHEADS + h];
        }
        __syncthreads();
        #pragma unroll
        for (int q = 0; q < 8; q++) {
            int jl = pg * 8 + q;
            int j = j0 + jl;
            float a = 0.f;
            if (j <= i) a = sc_base[j] * __expf(cum_i - cj[jl]) * dtj[jl];
            att[il][jl] = a;
        }
        __syncthreads();
        #pragma unroll 4
        for (int jl = 0; jl < 32; jl++) {
            float a = att[il][jl];
            #pragma unroll
            for (int p = 0; p < 32; p++) acc[p] = fmaf(a, xs[jl][pbase + p], acc[p]);
        }
    }

    // inter-chunk: += exp(cum_i) * sum_n C[i,n] * prev[h,p,n]
    float ei = __expf(cum_i);
    float (*prevs)[132] = xs;                         // reuse (16 rows used)
    float (*Ci)[17] = (float (*)[17]) & att[0][0];    // 64x17 fits in att
    size_t pv_base = (size_t)(bc * NHEADS + h) * (HEADDIM * D_STATE);
    for (int n0 = 0; n0 < 64; n0 += 16) {
        __syncthreads();
        for (int idx = threadIdx.x; idx < 16 * 128; idx += 256) {
            int nn = idx & 15, p = idx >> 4;
            prevs[nn][p] = g_prev[pv_base + (size_t)p * 64 + n0 + nn];
        }
        for (int idx = threadIdx.x; idx < 64 * 16; idx += 256) {
            int r = idx >> 4, nn = idx & 15;
            Ci[r][nn] = g_xbc[(size_t)(t0 + i0 + r) * CONV_DIM + D_INNER + D_STATE + n0 + nn];
        }
        __syncthreads();
        #pragma unroll
        for (int nn = 0; nn < 16; nn++) {
            float cv = Ci[il][nn] * ei;
            #pragma unroll
            for (int p = 0; p < 32; p++) acc[p] = fmaf(cv, prevs[nn][pbase + p], acc[p]);
        }
    }

    float Dh = Dv[h];
    float* yout = g_y + (size_t)ti * D_INNER + h * HEADDIM + pbase;
    const float* xrow = g_xbc + (size_t)ti * CONV_DIM + h * HEADDIM + pbase;
    #pragma unroll
    for (int p = 0; p < 32; p++) yout[p] = acc[p] + Dh * xrow[p];
}

// ---------------- gating + rmsnorm (in place on g_y, tf32-rounded) -----------
__global__ void __launch_bounds__(256) gate_rms_k(const float* __restrict__ rms_w) {
    int t = blockIdx.x;
    float v[8]; float ss = 0.f, dummy = 0.f;
    const float* yrow = g_y + (size_t)t * D_INNER;
    const float* zrow = g_zx + (size_t)t * D_IN_PROJ;
    #pragma unroll
    for (int k = 0; k < 8; k++) {
        int idx = threadIdx.x + k * 256;
        float z = zrow[idx];
        float gv = yrow[idx] * (z / (1.f + __expf(-z)));
        v[k] = gv; ss += gv * gv;
    }
    block_reduce2(ss, dummy);
    float scale = rsqrtf(ss * (1.f / D_INNER) + 1e-5f);
    float* grow = g_y + (size_t)t * D_INNER;
    #pragma unroll
    for (int k = 0; k < 8; k++) {
        int idx = threadIdx.x + k * 256;
        grow[idx] = to_tf32(v[k] * scale * rms_w[idx]);
    }
}

// ---------------- host launch -------------------------------------------------
extern "C" void kernel_launch(void* const* d_in, const int* in_sizes, int n_in,
                              void* d_out, int out_size) {
    (void)in_sizes; (void)n_in; (void)out_size;
    const float* u        = (const float*)d_in[0];
    const float* in_proj  = (const float*)d_in[1];
    const float* conv_w   = (const float*)d_in[2];
    const float* conv_b   = (const float*)d_in[3];
    const float* dt_bias  = (const float*)d_in[4];
    const float* A_log    = (const float*)d_in[5];
    const float* Dv       = (const float*)d_in[6];
    const float* xnw      = (const float*)d_in[7];
    const float* xnb      = (const float*)d_in[8];
    const float* rms_w    = (const float*)d_in[9];
    const float* out_proj = (const float*)d_in[10];
    float* out = (float*)d_out;

    void *p_w1n, *p_w2n, *p_uln, *p_zx, *p_y;
    cudaGetSymbolAddress(&p_w1n, g_w1n);
    cudaGetSymbolAddress(&p_w2n, g_w2n);
    cudaGetSymbolAddress(&p_uln, g_uln);
    cudaGetSymbolAddress(&p_zx,  g_zx);
    cudaGetSymbolAddress(&p_y,   g_y);

    static int smem_set = 0;
    if (!smem_set) {
        cudaFuncSetAttribute(gemm_tf32_nt,
                             cudaFuncAttributeMaxDynamicSharedMemorySize, GEMM_SMEM);
        smem_set = 1;
    }

    l2norm_rows_k<<<D_IN_PROJ, 256>>>(in_proj, (float*)p_w1n, DIMX, 0.03125f); // fold DIM^-0.5
    l2norm_rows_k<<<DIMX, 256>>>(out_proj, (float*)p_w2n, D_INNER, 1.0f);
    layernorm_k<<<NT, 256>>>(u, xnw, xnb);

    gemm_tf32_nt<<<dim3((D_IN_PROJ + 127) / 128, NT / 128), 256, GEMM_SMEM>>>(
        (const float*)p_uln, (const float*)p_w1n, (float*)p_zx, NT, D_IN_PROJ, DIMX);

    dtcum_k<<<NBC * NHEADS, 256>>>(dt_bias, A_log);
    conv_silu_k<<<dim3(NT, (CONV_DIM + 255) / 256), 256>>>(conv_w, conv_b);
    scores_k<<<dim3(NBC, 8), 256>>>();
    states_k<<<NBC * NHEADS, 256>>>();
    chunkscan_k<<<BATCHN * NHEADS, 256>>>();
    y_k<<<dim3(NBC * NHEADS, 4), 256>>>(Dv);
    gate_rms_k<<<NT, 256>>>(rms_w);

    gemm_tf32_nt<<<dim3(DIMX / 128, NT / 128), 256, GEMM_SMEM>>>(
        (const float*)p_y, (const float*)p_w2n, out, NT, DIMX, D_INNER);
}

// round 13
// speedup vs baseline: 1.7027x; 1.0000x over previous
#include <cuda_runtime.h>
#include <cstdint>

#define DIMX      1024
#define D_INNER   2048
#define NHEADS    16
#define HEADDIM   128
#define D_STATE   64
#define CONV_DIM  2176      // D_INNER + 2*D_STATE
#define D_IN_PROJ 4240      // 2*D_INNER + 2*D_STATE + NHEADS
#define CHUNKL    256
#define NCHUNK    16        // per batch (4096/256)
#define BATCHN    2
#define SEQLENN   4096
#define NT        8192      // BATCH*SEQLEN tokens
#define NBC       32        // BATCH*NCHUNK

// ---------------- scratch (static device memory; no runtime allocation) ----
__device__ float g_w1n[(size_t)D_IN_PROJ * DIMX];        // normalized in_proj (scale folded, tf32-rounded)
__device__ float g_w2n[(size_t)DIMX * D_INNER];          // normalized out_proj (tf32-rounded)
__device__ float g_uln[(size_t)NT * DIMX];               // layernormed input (tf32-rounded)
__device__ float g_zx [(size_t)NT * D_IN_PROJ];          // zxbcdt
__device__ float g_xbc[(size_t)NT * CONV_DIM];           // conv+silu output
__device__ float g_dt [(size_t)NT * NHEADS];
__device__ float g_cum[(size_t)NT * NHEADS];             // in-chunk inclusive cumsum of dt*A
__device__ float g_scores[(size_t)NBC * CHUNKL * CHUNKL];
__device__ float g_states[(size_t)NBC * NHEADS * HEADDIM * D_STATE];
__device__ float g_prev  [(size_t)NBC * NHEADS * HEADDIM * D_STATE];
__device__ float g_y  [(size_t)NT * D_INNER];            // y, then g (in place, tf32-rounded)

// ---------------- helpers ---------------------------------------------------
__device__ __forceinline__ float to_tf32(float x) {
    float r;
    asm("cvt.rna.tf32.f32 %0, %1;" : "=f"(r) : "f"(x));
    return r;
}

__device__ __forceinline__ void cp_async16(void* smem_dst, const void* gmem_src, int src_sz) {
    uint32_t s = (uint32_t)__cvta_generic_to_shared(smem_dst);
    asm volatile("cp.async.cg.shared.global [%0], [%1], 16, %2;"
                 :: "r"(s), "l"(gmem_src), "r"(src_sz));
}
__device__ __forceinline__ void cp_commit() { asm volatile("cp.async.commit_group;"); }
template <int N> __device__ __forceinline__ void cp_wait() {
    asm volatile("cp.async.wait_group %0;" :: "n"(N));
}

__device__ __forceinline__ uint32_t smem_u32(const void* p) {
    return (uint32_t)__cvta_generic_to_shared(p);
}

__device__ __forceinline__ void ldsm4(uint32_t* r, uint32_t addr) {
    asm volatile("ldmatrix.sync.aligned.m8n8.x4.shared.b16 {%0,%1,%2,%3}, [%4];"
                 : "=r"(r[0]), "=r"(r[1]), "=r"(r[2]), "=r"(r[3]) : "r"(addr));
}

__device__ __forceinline__ void mma_tf32(float* c, const uint32_t* a,
                                         uint32_t b0, uint32_t b1) {
    asm volatile("mma.sync.aligned.m16n8k8.row.col.f32.tf32.tf32.f32 "
                 "{%0,%1,%2,%3}, {%4,%5,%6,%7}, {%8,%9}, {%0,%1,%2,%3};"
                 : "+f"(c[0]), "+f"(c[1]), "+f"(c[2]), "+f"(c[3])
                 : "r"(a[0]), "r"(a[1]), "r"(a[2]), "r"(a[3]), "r"(b0), "r"(b1));
}

__device__ __forceinline__ void block_reduce2(float& a, float& b) {
    __shared__ float sa[32], sb[32];
    int lane = threadIdx.x & 31, w = threadIdx.x >> 5;
    #pragma unroll
    for (int o = 16; o; o >>= 1) {
        a += __shfl_down_sync(0xffffffffu, a, o);
        b += __shfl_down_sync(0xffffffffu, b, o);
    }
    if (lane == 0) { sa[w] = a; sb[w] = b; }
    __syncthreads();
    if (w == 0) {
        int nw = blockDim.x >> 5;
        a = (lane < nw) ? sa[lane] : 0.f;
        b = (lane < nw) ? sb[lane] : 0.f;
        #pragma unroll
        for (int o = 16; o; o >>= 1) {
            a += __shfl_down_sync(0xffffffffu, a, o);
            b += __shfl_down_sync(0xffffffffu, b, o);
        }
        if (lane == 0) { sa[0] = a; sb[0] = b; }
    }
    __syncthreads();
    a = sa[0]; b = sb[0];
}

// ---------------- weight l2-normalization (tf32-rounded output) -------------
__global__ void __launch_bounds__(256) l2norm_rows_k(const float* __restrict__ W,
                                                     float* __restrict__ out,
                                                     int K, float extra) {
    int row = blockIdx.x;
    const float* src = W + (size_t)row * K;
    float ss = 0.f, dummy = 0.f;
    for (int i = threadIdx.x; i < K; i += blockDim.x) { float v = src[i]; ss += v * v; }
    block_reduce2(ss, dummy);
    float scale = extra / fmaxf(sqrtf(ss), 1e-6f);
    float* dst = out + (size_t)row * K;
    for (int i = threadIdx.x; i < K; i += blockDim.x) dst[i] = to_tf32(src[i] * scale);
}

// ---------------- input layernorm (tf32-rounded output) ---------------------
__global__ void __launch_bounds__(256) layernorm_k(const float* __restrict__ u,
                                                   const float* __restrict__ w,
                                                   const float* __restrict__ b) {
    int t = blockIdx.x;
    const float* x = u + (size_t)t * DIMX;
    float v[4]; float s = 0.f, s2 = 0.f;
    #pragma unroll
    for (int k = 0; k < 4; k++) {
        v[k] = x[threadIdx.x + k * 256];
        s += v[k]; s2 += v[k] * v[k];
    }
    block_reduce2(s, s2);
    float mu = s * (1.f / DIMX);
    float var = s2 * (1.f / DIMX) - mu * mu;
    float inv = rsqrtf(var + 1e-5f);
    float* o = g_uln + (size_t)t * DIMX;
    #pragma unroll
    for (int k = 0; k < 4; k++) {
        int i = threadIdx.x + k * 256;
        o[i] = to_tf32((v[k] - mu) * inv * w[i] + b[i]);
    }
}

// ---------------- tf32 GEMM: C[M,N] = A[M,K] * B[N,K]^T ----------------------
// 128x128 block tile, BK=32, 3-stage cp.async pipeline, 8 warps (2x4),
// warp tile 64x32, ldmatrix.x4 + mma.m16n8k8.tf32. 2 CTAs/SM.
#define GSTAGES 3
#define ASF (128 * 36)
#define BSF (128 * 36)
#define STAGE_F (ASF + BSF)
#define GEMM_SMEM (GSTAGES * STAGE_F * 4)

__device__ __forceinline__ void gemm_load_stage(float* stage,
                                                const float* __restrict__ A,
                                                const float* __restrict__ B,
                                                int bm, int bn, int k0,
                                                int N, int K, int tid) {
    float* As = stage;
    float* Bs = stage + ASF;
    #pragma unroll
    for (int u = 0; u < 4; u++) {           // A: 128x32 = 1024 float4
        int idx = tid + u * 256;
        int r = idx >> 3, cc = (idx & 7) * 4;
        cp_async16(&As[r * 36 + cc], A + (size_t)(bm + r) * K + k0 + cc, 16);
    }
    #pragma unroll
    for (int u = 0; u < 4; u++) {           // B: 128x32 = 1024 float4
        int idx = tid + u * 256;
        int r = idx >> 3, cc = (idx & 7) * 4;
        int brow = bn + r;
        int safe = (brow < N) ? brow : (N - 1);
        cp_async16(&Bs[r * 36 + cc], B + (size_t)safe * K + k0 + cc, (brow < N) ? 16 : 0);
    }
    cp_commit();
}

__global__ void __launch_bounds__(256, 2) gemm_tf32_nt(const float* __restrict__ A,
                                                       const float* __restrict__ B,
                                                       float* __restrict__ C,
                                                       int M, int N, int K) {
    extern __shared__ float sm[];
    int bm = blockIdx.y * 128;
    int bn = blockIdx.x * 128;
    int tid = threadIdx.x;
    int warp = tid >> 5;
    int lane = tid & 31;
    int wm = (warp >> 2) * 64;               // 2 m-groups of 64
    int wn = (warp & 3) * 32;                // 4 n-groups of 32

    // ldmatrix lane-address components
    int a_row = lane & 15;
    int a_ko  = (lane >> 4) * 4;
    int b_n   = (lane & 7) + ((lane & 16) >> 1);
    int b_ko  = ((lane >> 3) & 1) * 4;

    float c[4][4][4];                        // [m16-block][n8-block][regs]
    #pragma unroll
    for (int i = 0; i < 4; i++)
        #pragma unroll
        for (int j = 0; j < 4; j++)
            #pragma unroll
            for (int r = 0; r < 4; r++) c[i][j][r] = 0.f;

    int kTiles = K >> 5;
    #pragma unroll
    for (int s = 0; s < GSTAGES - 1; s++)
        gemm_load_stage(sm + s * STAGE_F, A, B, bm, bn, s * 32, N, K, tid);

    for (int kt = 0; kt < kTiles; kt++) {
        cp_wait<GSTAGES - 2>();
        __syncthreads();
        int nk = kt + GSTAGES - 1;
        if (nk < kTiles)
            gemm_load_stage(sm + (nk % GSTAGES) * STAGE_F, A, B, bm, bn,
                            nk * 32, N, K, tid);

        const float* As = sm + (kt % GSTAGES) * STAGE_F;
        const float* Bs = As + ASF;
        #pragma unroll
        for (int ks = 0; ks < 32; ks += 8) {
            uint32_t a[4][4];
            #pragma unroll
            for (int i = 0; i < 4; i++)
                ldsm4(a[i], smem_u32(&As[(wm + i * 16 + a_row) * 36 + ks + a_ko]));
            #pragma unroll
            for (int jb = 0; jb < 2; jb++) {
                uint32_t b[4];
                ldsm4(b, smem_u32(&Bs[(wn + jb * 16 + b_n) * 36 + ks + b_ko]));
                #pragma unroll
                for (int i = 0; i < 4; i++) {
                    mma_tf32(c[i][2 * jb],     a[i], b[0], b[1]);
                    mma_tf32(c[i][2 * jb + 1], a[i], b[2], b[3]);
                }
            }
        }
    }
    __syncthreads();

    // epilogue: thread holds rows (t/4, t/4+8), cols 2*(t%4)+{0,1} per 16x8 tile
    int t4 = lane >> 2;
    int t2 = (lane & 3) * 2;
    #pragma unroll
    for (int i = 0; i < 4; i++) {
        #pragma unroll
        for (int j = 0; j < 4; j++) {
            int col = bn + wn + j * 8 + t2;
            if (col < N) {
                size_t r0 = (size_t)(bm + wm + i * 16 + t4) * N + col;
                size_t r1 = r0 + (size_t)8 * N;
                *(float2*)&C[r0] = make_float2(c[i][j][0], c[i][j][1]);
                *(float2*)&C[r1] = make_float2(c[i][j][2], c[i][j][3]);
            }
        }
    }
}

// ---------------- dt = softplus(raw + bias); cum = cumsum(dt*A) per chunk ----
__global__ void __launch_bounds__(256) dtcum_k(const float* __restrict__ dt_bias,
                                               const float* __restrict__ A_log) {
    int h = blockIdx.x & 15, bc = blockIdx.x >> 4;
    int t = bc * CHUNKL + threadIdx.x;
    float raw = g_zx[(size_t)t * D_IN_PROJ + (D_INNER + CONV_DIM) + h] + dt_bias[h];
    float dt = (raw > 20.f) ? raw : log1pf(expf(raw));
    g_dt[t * NHEADS + h] = dt;
    float dA = dt * (-expf(A_log[h]));
    __shared__ float sc[CHUNKL];
    sc[threadIdx.x] = dA;
    __syncthreads();
    for (int off = 1; off < CHUNKL; off <<= 1) {
        float add = (threadIdx.x >= off) ? sc[threadIdx.x - off] : 0.f;
        __syncthreads();
        sc[threadIdx.x] += add;
        __syncthreads();
    }
    g_cum[t * NHEADS + h] = sc[threadIdx.x];
}

// ---------------- causal depthwise conv (w=4) + SiLU -------------------------
__global__ void __launch_bounds__(256) conv_silu_k(const float* __restrict__ cw,
                                                   const float* __restrict__ cb) {
    int t = blockIdx.x;
    int ch = blockIdx.y * 256 + threadIdx.x;
    if (ch >= CONV_DIM) return;
    int l = t & (SEQLENN - 1);
    float acc = cb[ch];
    #pragma unroll
    for (int j = 0; j < 4; j++) {
        int ll = l - 3 + j;
        if (ll >= 0)
            acc = fmaf(cw[ch * 4 + j], g_zx[(size_t)(t - 3 + j) * D_IN_PROJ + D_INNER + ch], acc);
    }
    float sv = acc / (1.f + __expf(-acc));
    g_xbc[(size_t)t * CONV_DIM + ch] = sv;
}

// ---------------- scores[i,j] = C_i . B_j (lower triangle tiles only) --------
__global__ void __launch_bounds__(256) scores_k() {
    int bc = blockIdx.x;
    int i0 = blockIdx.y * 32;
    int t0 = bc * CHUNKL;
    __shared__ float Cs[32][65];
    __shared__ float Bs[64][65];
    for (int idx = threadIdx.x; idx < 32 * 64; idx += 256) {
        int r = idx >> 6, n = idx & 63;
        Cs[r][n] = g_xbc[(size_t)(t0 + i0 + r) * CONV_DIM + D_INNER + D_STATE + n];
    }
    for (int j0 = 0; j0 <= i0 + 31; j0 += 64) {
        __syncthreads();
        for (int idx = threadIdx.x; idx < 64 * 64; idx += 256) {
            int r = idx >> 6, n = idx & 63;
            Bs[r][n] = g_xbc[(size_t)(t0 + j0 + r) * CONV_DIM + D_INNER + n];
        }
        __syncthreads();
        #pragma unroll
        for (int q = 0; q < 8; q++) {
            int o = threadIdx.x + q * 256;
            int ii = o >> 6, jj = o & 63;
            float acc = 0.f;
            #pragma unroll
            for (int n = 0; n < 64; n++) acc = fmaf(Cs[ii][n], Bs[jj][n], acc);
            g_scores[(size_t)bc * 65536 + (size_t)(i0 + ii) * 256 + (j0 + jj)] = acc;
        }
    }
}

// ---------------- chunk-end states: state[p,n] = sum_l x[l,p]*dt*decay*B[l,n]-
__global__ void __launch_bounds__(256) states_k() {
    int h = blockIdx.x & 15, bc = blockIdx.x >> 4;
    int t0 = bc * CHUNKL;
    float cum_last = g_cum[(t0 + CHUNKL - 1) * NHEADS + h];
    int n = threadIdx.x & 63;
    int pbase = (threadIdx.x >> 6) * 32;
    float acc[32];
    #pragma unroll
    for (int p = 0; p < 32; p++) acc[p] = 0.f;
    __shared__ float xs[32][128];
    __shared__ float Bs[32][65];
    __shared__ float coef[32];
    for (int l0 = 0; l0 < CHUNKL; l0 += 32) {
        __syncthreads();
        for (int idx = threadIdx.x; idx < 32 * 128; idx += 256) {
            int r = idx >> 7, p = idx & 127;
            xs[r][p] = g_xbc[(size_t)(t0 + l0 + r) * CONV_DIM + h * HEADDIM + p];
        }
        for (int idx = threadIdx.x; idx < 32 * 64; idx += 256) {
            int r = idx >> 6, nn = idx & 63;
            Bs[r][nn] = g_xbc[(size_t)(t0 + l0 + r) * CONV_DIM + D_INNER + nn];
        }
        if (threadIdx.x < 32) {
            int tt = t0 + l0 + threadIdx.x;
            coef[threadIdx.x] = g_dt[tt * NHEADS + h] * __expf(cum_last - g_cum[tt * NHEADS + h]);
        }
        __syncthreads();
        #pragma unroll 4
        for (int l = 0; l < 32; l++) {
            float bn = Bs[l][n] * coef[l];
            #pragma unroll
            for (int p = 0; p < 32; p++) acc[p] = fmaf(xs[l][pbase + p], bn, acc[p]);
        }
    }
    size_t base = (size_t)blockIdx.x * (HEADDIM * D_STATE);
    #pragma unroll
    for (int p = 0; p < 32; p++) g_states[base + (size_t)(pbase + p) * 64 + n] = acc[p];
}

// ---------------- sequential inter-chunk scan (per b,h) ----------------------
__global__ void __launch_bounds__(256) chunkscan_k() {
    int h = blockIdx.x & 15, b = blockIdx.x >> 4;
    float s[32];
    #pragma unroll
    for (int k = 0; k < 32; k++) s[k] = 0.f;
    for (int c = 0; c < NCHUNK; c++) {
        int bc = b * NCHUNK + c;
        size_t base = (size_t)(bc * NHEADS + h) * (HEADDIM * D_STATE);
        float dec = __expf(g_cum[(bc * CHUNKL + CHUNKL - 1) * NHEADS + h]);
        #pragma unroll
        for (int k = 0; k < 32; k++) {
            size_t idx = base + threadIdx.x + k * 256;
            g_prev[idx] = s[k];
            s[k] = s[k] * dec + g_states[idx];
        }
    }
}

// ---------------- y = intra + inter + D*x ------------------------------------
__global__ void __launch_bounds__(256) y_k(const float* __restrict__ Dv) {
    int h = blockIdx.x & 15, bc = blockIdx.x >> 4;
    int i0 = blockIdx.y * 64;
    int t0 = bc * CHUNKL;
    int il = threadIdx.x & 63;
    int pg = threadIdx.x >> 6;
    int pbase = pg * 32;
    int i = i0 + il;
    int ti = t0 + i;
    float cum_i = g_cum[ti * NHEADS + h];
    float acc[32];
    #pragma unroll
    for (int p = 0; p < 32; p++) acc[p] = 0.f;
    __shared__ float xs[32][132];
    __shared__ float att[64][33];
    __shared__ float cj[32];
    __shared__ float dtj[32];
    const float* sc_base = g_scores + (size_t)bc * 65536 + (size_t)i * 256;

    // intra-chunk: sum_{j<=i} scores[i,j]*exp(cum_i-cum_j)*dt_j * x[j,:]
    for (int j0 = 0; j0 < i0 + 64; j0 += 32) {
        __syncthreads();
        for (int idx = threadIdx.x; idx < 32 * 128; idx += 256) {
            int r = idx >> 7, p = idx & 127;
            xs[r][p] = g_xbc[(size_t)(t0 + j0 + r) * CONV_DIM + h * HEADDIM + p];
        }
        if (threadIdx.x < 32) {
            int tt = t0 + j0 + threadIdx.x;
            cj[threadIdx.x]  = g_cum[tt * NHEADS + h];
            dtj[threadIdx.x] = g_dt[tt * NHEADS + h];
        }
        __syncthreads();
        #pragma unroll
        for (int q = 0; q < 8; q++) {
            int jl = pg * 8 + q;
            int j = j0 + jl;
            float a = 0.f;
            if (j <= i) a = sc_base[j] * __expf(cum_i - cj[jl]) * dtj[jl];
            att[il][jl] = a;
        }
        __syncthreads();
        #pragma unroll 4
        for (int jl = 0; jl < 32; jl++) {
            float a = att[il][jl];
            #pragma unroll
            for (int p = 0; p < 32; p++) acc[p] = fmaf(a, xs[jl][pbase + p], acc[p]);
        }
    }

    // inter-chunk: += exp(cum_i) * sum_n C[i,n] * prev[h,p,n]
    float ei = __expf(cum_i);
    float (*prevs)[132] = xs;                         // reuse (16 rows used)
    float (*Ci)[17] = (float (*)[17]) & att[0][0];    // 64x17 fits in att
    size_t pv_base = (size_t)(bc * NHEADS + h) * (HEADDIM * D_STATE);
    for (int n0 = 0; n0 < 64; n0 += 16) {
        __syncthreads();
        for (int idx = threadIdx.x; idx < 16 * 128; idx += 256) {
            int nn = idx & 15, p = idx >> 4;
            prevs[nn][p] = g_prev[pv_base + (size_t)p * 64 + n0 + nn];
        }
        for (int idx = threadIdx.x; idx < 64 * 16; idx += 256) {
            int r = idx >> 4, nn = idx & 15;
            Ci[r][nn] = g_xbc[(size_t)(t0 + i0 + r) * CONV_DIM + D_INNER + D_STATE + n0 + nn];
        }
        __syncthreads();
        #pragma unroll
        for (int nn = 0; nn < 16; nn++) {
            float cv = Ci[il][nn] * ei;
            #pragma unroll
            for (int p = 0; p < 32; p++) acc[p] = fmaf(cv, prevs[nn][pbase + p], acc[p]);
        }
    }

    float Dh = Dv[h];
    float* yout = g_y + (size_t)ti * D_INNER + h * HEADDIM + pbase;
    const float* xrow = g_xbc + (size_t)ti * CONV_DIM + h * HEADDIM + pbase;
    #pragma unroll
    for (int p = 0; p < 32; p++) yout[p] = acc[p] + Dh * xrow[p];
}

// ---------------- gating + rmsnorm (in place on g_y, tf32-rounded) -----------
__global__ void __launch_bounds__(256) gate_rms_k(const float* __restrict__ rms_w) {
    int t = blockIdx.x;
    float v[8]; float ss = 0.f, dummy = 0.f;
    const float* yrow = g_y + (size_t)t * D_INNER;
    const float* zrow = g_zx + (size_t)t * D_IN_PROJ;
    #pragma unroll
    for (int k = 0; k < 8; k++) {
        int idx = threadIdx.x + k * 256;
        float z = zrow[idx];
        float gv = yrow[idx] * (z / (1.f + __expf(-z)));
        v[k] = gv; ss += gv * gv;
    }
    block_reduce2(ss, dummy);
    float scale = rsqrtf(ss * (1.f / D_INNER) + 1e-5f);
    float* grow = g_y + (size_t)t * D_INNER;
    #pragma unroll
    for (int k = 0; k < 8; k++) {
        int idx = threadIdx.x + k * 256;
        grow[idx] = to_tf32(v[k] * scale * rms_w[idx]);
    }
}

// ---------------- host launch -------------------------------------------------
extern "C" void kernel_launch(void* const* d_in, const int* in_sizes, int n_in,
                              void* d_out, int out_size) {
    (void)in_sizes; (void)n_in; (void)out_size;
    const float* u        = (const float*)d_in[0];
    const float* in_proj  = (const float*)d_in[1];
    const float* conv_w   = (const float*)d_in[2];
    const float* conv_b   = (const float*)d_in[3];
    const float* dt_bias  = (const float*)d_in[4];
    const float* A_log    = (const float*)d_in[5];
    const float* Dv       = (const float*)d_in[6];
    const float* xnw      = (const float*)d_in[7];
    const float* xnb      = (const float*)d_in[8];
    const float* rms_w    = (const float*)d_in[9];
    const float* out_proj = (const float*)d_in[10];
    float* out = (float*)d_out;

    void *p_w1n, *p_w2n, *p_uln, *p_zx, *p_y;
    cudaGetSymbolAddress(&p_w1n, g_w1n);
    cudaGetSymbolAddress(&p_w2n, g_w2n);
    cudaGetSymbolAddress(&p_uln, g_uln);
    cudaGetSymbolAddress(&p_zx,  g_zx);
    cudaGetSymbolAddress(&p_y,   g_y);

    static int smem_set = 0;
    if (!smem_set) {
        cudaFuncSetAttribute(gemm_tf32_nt,
                             cudaFuncAttributeMaxDynamicSharedMemorySize, GEMM_SMEM);
        smem_set = 1;
    }

    l2norm_rows_k<<<D_IN_PROJ, 256>>>(in_proj, (float*)p_w1n, DIMX, 0.03125f); // fold DIM^-0.5
    l2norm_rows_k<<<DIMX, 256>>>(out_proj, (float*)p_w2n, D_INNER, 1.0f);
    layernorm_k<<<NT, 256>>>(u, xnw, xnb);

    gemm_tf32_nt<<<dim3((D_IN_PROJ + 127) / 128, NT / 128), 256, GEMM_SMEM>>>(
        (const float*)p_uln, (const float*)p_w1n, (float*)p_zx, NT, D_IN_PROJ, DIMX);

    dtcum_k<<<NBC * NHEADS, 256>>>(dt_bias, A_log);
    conv_silu_k<<<dim3(NT, (CONV_DIM + 255) / 256), 256>>>(conv_w, conv_b);
    scores_k<<<dim3(NBC, 8), 256>>>();
    states_k<<<NBC * NHEADS, 256>>>();
    chunkscan_k<<<BATCHN * NHEADS, 256>>>();
    y_k<<<dim3(NBC * NHEADS, 4), 256>>>(Dv);
    gate_rms_k<<<NT, 256>>>(rms_w);

    gemm_tf32_nt<<<dim3(DIMX / 128, NT / 128), 256, GEMM_SMEM>>>(
        (const float*)p_y, (const float*)p_w2n, out, NT, DIMX, D_INNER);
}

// round 14
// speedup vs baseline: 1.7037x; 1.0006x over previous
#include <cuda_runtime.h>
#include <cstdint>

#define DIMX      1024
#define D_INNER   2048
#define NHEADS    16
#define HEADDIM   128
#define D_STATE   64
#define CONV_DIM  2176      // D_INNER + 2*D_STATE
#define D_IN_PROJ 4240      // 2*D_INNER + 2*D_STATE + NHEADS
#define CHUNKL    256
#define NCHUNK    16        // per batch (4096/256)
#define BATCHN    2
#define SEQLENN   4096
#define NT        8192      // BATCH*SEQLEN tokens
#define NBC       32        // BATCH*NCHUNK

// ---------------- scratch (static device memory; no runtime allocation) ----
__device__ float g_w1n[(size_t)D_IN_PROJ * DIMX];        // normalized in_proj (scale folded, tf32-rounded)
__device__ float g_w2n[(size_t)DIMX * D_INNER];          // normalized out_proj (tf32-rounded)
__device__ float g_uln[(size_t)NT * DIMX];               // layernormed input (tf32-rounded)
__device__ float g_zx [(size_t)NT * D_IN_PROJ];          // zxbcdt
__device__ float g_xbc[(size_t)NT * CONV_DIM];           // conv+silu output
__device__ float g_dt [(size_t)NT * NHEADS];
__device__ float g_cum[(size_t)NT * NHEADS];             // in-chunk inclusive cumsum of dt*A
__device__ float g_scores[(size_t)NBC * CHUNKL * CHUNKL];
__device__ float g_states[(size_t)NBC * NHEADS * HEADDIM * D_STATE];
__device__ float g_prev  [(size_t)NBC * NHEADS * HEADDIM * D_STATE];
__device__ float g_y  [(size_t)NT * D_INNER];            // y, then g (in place, tf32-rounded)

// ---------------- helpers ---------------------------------------------------
__device__ __forceinline__ float to_tf32(float x) {
    float r;
    asm("cvt.rna.tf32.f32 %0, %1;" : "=f"(r) : "f"(x));
    return r;
}

__device__ __forceinline__ void cp_async16(void* smem_dst, const void* gmem_src, int src_sz) {
    uint32_t s = (uint32_t)__cvta_generic_to_shared(smem_dst);
    asm volatile("cp.async.cg.shared.global [%0], [%1], 16, %2;"
                 :: "r"(s), "l"(gmem_src), "r"(src_sz));
}
__device__ __forceinline__ void cp_commit() { asm volatile("cp.async.commit_group;"); }
template <int N> __device__ __forceinline__ void cp_wait() {
    asm volatile("cp.async.wait_group %0;" :: "n"(N));
}

__device__ __forceinline__ uint32_t smem_u32(const void* p) {
    return (uint32_t)__cvta_generic_to_shared(p);
}

__device__ __forceinline__ void ldsm4(uint32_t* r, uint32_t addr) {
    asm volatile("ldmatrix.sync.aligned.m8n8.x4.shared.b16 {%0,%1,%2,%3}, [%4];"
                 : "=r"(r[0]), "=r"(r[1]), "=r"(r[2]), "=r"(r[3]) : "r"(addr));
}

__device__ __forceinline__ void mma_tf32(float* c, const uint32_t* a,
                                         uint32_t b0, uint32_t b1) {
    asm volatile("mma.sync.aligned.m16n8k8.row.col.f32.tf32.tf32.f32 "
                 "{%0,%1,%2,%3}, {%4,%5,%6,%7}, {%8,%9}, {%0,%1,%2,%3};"
                 : "+f"(c[0]), "+f"(c[1]), "+f"(c[2]), "+f"(c[3])
                 : "r"(a[0]), "r"(a[1]), "r"(a[2]), "r"(a[3]), "r"(b0), "r"(b1));
}

__device__ __forceinline__ void block_reduce2(float& a, float& b) {
    __shared__ float sa[32], sb[32];
    int lane = threadIdx.x & 31, w = threadIdx.x >> 5;
    #pragma unroll
    for (int o = 16; o; o >>= 1) {
        a += __shfl_down_sync(0xffffffffu, a, o);
        b += __shfl_down_sync(0xffffffffu, b, o);
    }
    if (lane == 0) { sa[w] = a; sb[w] = b; }
    __syncthreads();
    if (w == 0) {
        int nw = blockDim.x >> 5;
        a = (lane < nw) ? sa[lane] : 0.f;
        b = (lane < nw) ? sb[lane] : 0.f;
        #pragma unroll
        for (int o = 16; o; o >>= 1) {
            a += __shfl_down_sync(0xffffffffu, a, o);
            b += __shfl_down_sync(0xffffffffu, b, o);
        }
        if (lane == 0) { sa[0] = a; sb[0] = b; }
    }
    __syncthreads();
    a = sa[0]; b = sb[0];
}

// ---------------- weight l2-normalization (tf32-rounded output) -------------
__global__ void __launch_bounds__(256) l2norm_rows_k(const float* __restrict__ W,
                                                     float* __restrict__ out,
                                                     int K, float extra) {
    int row = blockIdx.x;
    const float* src = W + (size_t)row * K;
    float ss = 0.f, dummy = 0.f;
    for (int i = threadIdx.x; i < K; i += blockDim.x) { float v = src[i]; ss += v * v; }
    block_reduce2(ss, dummy);
    float scale = extra / fmaxf(sqrtf(ss), 1e-6f);
    float* dst = out + (size_t)row * K;
    for (int i = threadIdx.x; i < K; i += blockDim.x) dst[i] = to_tf32(src[i] * scale);
}

// ---------------- input layernorm (tf32-rounded output) ---------------------
__global__ void __launch_bounds__(256) layernorm_k(const float* __restrict__ u,
                                                   const float* __restrict__ w,
                                                   const float* __restrict__ b) {
    int t = blockIdx.x;
    const float* x = u + (size_t)t * DIMX;
    float v[4]; float s = 0.f, s2 = 0.f;
    #pragma unroll
    for (int k = 0; k < 4; k++) {
        v[k] = x[threadIdx.x + k * 256];
        s += v[k]; s2 += v[k] * v[k];
    }
    block_reduce2(s, s2);
    float mu = s * (1.f / DIMX);
    float var = s2 * (1.f / DIMX) - mu * mu;
    float inv = rsqrtf(var + 1e-5f);
    float* o = g_uln + (size_t)t * DIMX;
    #pragma unroll
    for (int k = 0; k < 4; k++) {
        int i = threadIdx.x + k * 256;
        o[i] = to_tf32((v[k] - mu) * inv * w[i] + b[i]);
    }
}

// ---------------- tf32 GEMM: C[M,N] = A[M,K] * B[N,K]^T ----------------------
// 128x128 block tile, BK=32, 3-stage cp.async pipeline, 8 warps (2x4),
// warp tile 64x32, ldmatrix.x4 + mma.m16n8k8.tf32. 2 CTAs/SM.
#define GSTAGES 3
#define ASF (128 * 36)
#define BSF (128 * 36)
#define STAGE_F (ASF + BSF)
#define GEMM_SMEM (GSTAGES * STAGE_F * 4)

__device__ __forceinline__ void gemm_load_stage(float* stage,
                                                const float* __restrict__ A,
                                                const float* __restrict__ B,
                                                int bm, int bn, int k0,
                                                int N, int K, int tid) {
    float* As = stage;
    float* Bs = stage + ASF;
    #pragma unroll
    for (int u = 0; u < 4; u++) {           // A: 128x32 = 1024 float4
        int idx = tid + u * 256;
        int r = idx >> 3, cc = (idx & 7) * 4;
        cp_async16(&As[r * 36 + cc], A + (size_t)(bm + r) * K + k0 + cc, 16);
    }
    #pragma unroll
    for (int u = 0; u < 4; u++) {           // B: 128x32 = 1024 float4
        int idx = tid + u * 256;
        int r = idx >> 3, cc = (idx & 7) * 4;
        int brow = bn + r;
        int safe = (brow < N) ? brow : (N - 1);
        cp_async16(&Bs[r * 36 + cc], B + (size_t)safe * K + k0 + cc, (brow < N) ? 16 : 0);
    }
    cp_commit();
}

__global__ void __launch_bounds__(256, 2) gemm_tf32_nt(const float* __restrict__ A,
                                                       const float* __restrict__ B,
                                                       float* __restrict__ C,
                                                       int M, int N, int K) {
    extern __shared__ float sm[];
    int bm = blockIdx.y * 128;
    int bn = blockIdx.x * 128;
    int tid = threadIdx.x;
    int warp = tid >> 5;
    int lane = tid & 31;
    int wm = (warp >> 2) * 64;               // 2 m-groups of 64
    int wn = (warp & 3) * 32;                // 4 n-groups of 32

    // ldmatrix lane-address components
    int a_row = lane & 15;
    int a_ko  = (lane >> 4) * 4;
    int b_n   = (lane & 7) + ((lane & 16) >> 1);
    int b_ko  = ((lane >> 3) & 1) * 4;

    float c[4][4][4];                        // [m16-block][n8-block][regs]
    #pragma unroll
    for (int i = 0; i < 4; i++)
        #pragma unroll
        for (int j = 0; j < 4; j++)
            #pragma unroll
            for (int r = 0; r < 4; r++) c[i][j][r] = 0.f;

    int kTiles = K >> 5;
    #pragma unroll
    for (int s = 0; s < GSTAGES - 1; s++)
        gemm_load_stage(sm + s * STAGE_F, A, B, bm, bn, s * 32, N, K, tid);

    for (int kt = 0; kt < kTiles; kt++) {
        cp_wait<GSTAGES - 2>();
        __syncthreads();
        int nk = kt + GSTAGES - 1;
        if (nk < kTiles)
            gemm_load_stage(sm + (nk % GSTAGES) * STAGE_F, A, B, bm, bn,
                            nk * 32, N, K, tid);

        const float* As = sm + (kt % GSTAGES) * STAGE_F;
        const float* Bs = As + ASF;
        #pragma unroll
        for (int ks = 0; ks < 32; ks += 8) {
            uint32_t a[4][4];
            #pragma unroll
            for (int i = 0; i < 4; i++)
                ldsm4(a[i], smem_u32(&As[(wm + i * 16 + a_row) * 36 + ks + a_ko]));
            #pragma unroll
            for (int jb = 0; jb < 2; jb++) {
                uint32_t b[4];
                ldsm4(b, smem_u32(&Bs[(wn + jb * 16 + b_n) * 36 + ks + b_ko]));
                #pragma unroll
                for (int i = 0; i < 4; i++) {
                    mma_tf32(c[i][2 * jb],     a[i], b[0], b[1]);
                    mma_tf32(c[i][2 * jb + 1], a[i], b[2], b[3]);
                }
            }
        }
    }
    __syncthreads();

    // epilogue: thread holds rows (t/4, t/4+8), cols 2*(t%4)+{0,1} per 16x8 tile
    int t4 = lane >> 2;
    int t2 = (lane & 3) * 2;
    #pragma unroll
    for (int i = 0; i < 4; i++) {
        #pragma unroll
        for (int j = 0; j < 4; j++) {
            int col = bn + wn + j * 8 + t2;
            if (col < N) {
                size_t r0 = (size_t)(bm + wm + i * 16 + t4) * N + col;
                size_t r1 = r0 + (size_t)8 * N;
                *(float2*)&C[r0] = make_float2(c[i][j][0], c[i][j][1]);
                *(float2*)&C[r1] = make_float2(c[i][j][2], c[i][j][3]);
            }
        }
    }
}

// ---------------- dt = softplus(raw + bias); cum = cumsum(dt*A) per chunk ----
__global__ void __launch_bounds__(256) dtcum_k(const float* __restrict__ dt_bias,
                                               const float* __restrict__ A_log) {
    int h = blockIdx.x & 15, bc = blockIdx.x >> 4;
    int t = bc * CHUNKL + threadIdx.x;
    float raw = g_zx[(size_t)t * D_IN_PROJ + (D_INNER + CONV_DIM) + h] + dt_bias[h];
    float dt = (raw > 20.f) ? raw : log1pf(expf(raw));
    g_dt[t * NHEADS + h] = dt;
    float dA = dt * (-expf(A_log[h]));
    __shared__ float sc[CHUNKL];
    sc[threadIdx.x] = dA;
    __syncthreads();
    for (int off = 1; off < CHUNKL; off <<= 1) {
        float add = (threadIdx.x >= off) ? sc[threadIdx.x - off] : 0.f;
        __syncthreads();
        sc[threadIdx.x] += add;
        __syncthreads();
    }
    g_cum[t * NHEADS + h] = sc[threadIdx.x];
}

// ---------------- causal depthwise conv (w=4) + SiLU -------------------------
__global__ void __launch_bounds__(256) conv_silu_k(const float* __restrict__ cw,
                                                   const float* __restrict__ cb) {
    int t = blockIdx.x;
    int ch = blockIdx.y * 256 + threadIdx.x;
    if (ch >= CONV_DIM) return;
    int l = t & (SEQLENN - 1);
    float acc = cb[ch];
    #pragma unroll
    for (int j = 0; j < 4; j++) {
        int ll = l - 3 + j;
        if (ll >= 0)
            acc = fmaf(cw[ch * 4 + j], g_zx[(size_t)(t - 3 + j) * D_IN_PROJ + D_INNER + ch], acc);
    }
    float sv = acc / (1.f + __expf(-acc));
    g_xbc[(size_t)t * CONV_DIM + ch] = sv;
}

// ---------------- scores[i,j] = C_i . B_j (lower triangle tiles only) --------
__global__ void __launch_bounds__(256) scores_k() {
    int bc = blockIdx.x;
    int i0 = blockIdx.y * 32;
    int t0 = bc * CHUNKL;
    __shared__ float Cs[32][65];
    __shared__ float Bs[64][65];
    for (int idx = threadIdx.x; idx < 32 * 64; idx += 256) {
        int r = idx >> 6, n = idx & 63;
        Cs[r][n] = g_xbc[(size_t)(t0 + i0 + r) * CONV_DIM + D_INNER + D_STATE + n];
    }
    for (int j0 = 0; j0 <= i0 + 31; j0 += 64) {
        __syncthreads();
        for (int idx = threadIdx.x; idx < 64 * 64; idx += 256) {
            int r = idx >> 6, n = idx & 63;
            Bs[r][n] = g_xbc[(size_t)(t0 + j0 + r) * CONV_DIM + D_INNER + n];
        }
        __syncthreads();
        #pragma unroll
        for (int q = 0; q < 8; q++) {
            int o = threadIdx.x + q * 256;
            int ii = o >> 6, jj = o & 63;
            float acc = 0.f;
            #pragma unroll
            for (int n = 0; n < 64; n++) acc = fmaf(Cs[ii][n], Bs[jj][n], acc);
            g_scores[(size_t)bc * 65536 + (size_t)(i0 + ii) * 256 + (j0 + jj)] = acc;
        }
    }
}

// ---------------- chunk-end states: state[p,n] = sum_l x[l,p]*dt*decay*B[l,n]-
__global__ void __launch_bounds__(256) states_k() {
    int h = blockIdx.x & 15, bc = blockIdx.x >> 4;
    int t0 = bc * CHUNKL;
    float cum_last = g_cum[(t0 + CHUNKL - 1) * NHEADS + h];
    int n = threadIdx.x & 63;
    int pbase = (threadIdx.x >> 6) * 32;
    float acc[32];
    #pragma unroll
    for (int p = 0; p < 32; p++) acc[p] = 0.f;
    __shared__ float xs[32][128];
    __shared__ float Bs[32][65];
    __shared__ float coef[32];
    for (int l0 = 0; l0 < CHUNKL; l0 += 32) {
        __syncthreads();
        for (int idx = threadIdx.x; idx < 32 * 128; idx += 256) {
            int r = idx >> 7, p = idx & 127;
            xs[r][p] = g_xbc[(size_t)(t0 + l0 + r) * CONV_DIM + h * HEADDIM + p];
        }
        for (int idx = threadIdx.x; idx < 32 * 64; idx += 256) {
            int r = idx >> 6, nn = idx & 63;
            Bs[r][nn] = g_xbc[(size_t)(t0 + l0 + r) * CONV_DIM + D_INNER + nn];
        }
        if (threadIdx.x < 32) {
            int tt = t0 + l0 + threadIdx.x;
            coef[threadIdx.x] = g_dt[tt * NHEADS + h] * __expf(cum_last - g_cum[tt * NHEADS + h]);
        }
        __syncthreads();
        #pragma unroll 4
        for (int l = 0; l < 32; l++) {
            float bn = Bs[l][n] * coef[l];
            #pragma unroll
            for (int p = 0; p < 32; p++) acc[p] = fmaf(xs[l][pbase + p], bn, acc[p]);
        }
    }
    size_t base = (size_t)blockIdx.x * (HEADDIM * D_STATE);
    #pragma unroll
    for (int p = 0; p < 32; p++) g_states[base + (size_t)(pbase + p) * 64 + n] = acc[p];
}

// ---------------- sequential inter-chunk scan (per b,h) ----------------------
__global__ void __launch_bounds__(256) chunkscan_k() {
    int h = blockIdx.x & 15, b = blockIdx.x >> 4;
    float s[32];
    #pragma unroll
    for (int k = 0; k < 32; k++) s[k] = 0.f;
    for (int c = 0; c < NCHUNK; c++) {
        int bc = b * NCHUNK + c;
        size_t base = (size_t)(bc * NHEADS + h) * (HEADDIM * D_STATE);
        float dec = __expf(g_cum[(bc * CHUNKL + CHUNKL - 1) * NHEADS + h]);
        #pragma unroll
        for (int k = 0; k < 32; k++) {
            size_t idx = base + threadIdx.x + k * 256;
            g_prev[idx] = s[k];
            s[k] = s[k] * dec + g_states[idx];
        }
    }
}

// ---------------- y = intra + inter + D*x ------------------------------------
__global__ void __launch_bounds__(256) y_k(const float* __restrict__ Dv) {
    int h = blockIdx.x & 15, bc = blockIdx.x >> 4;
    int i0 = blockIdx.y * 64;
    int t0 = bc * CHUNKL;
    int il = threadIdx.x & 63;
    int pg = threadIdx.x >> 6;
    int pbase = pg * 32;
    int i = i0 + il;
    int ti = t0 + i;
    float cum_i = g_cum[ti * NHEADS + h];
    float acc[32];
    #pragma unroll
    for (int p = 0; p < 32; p++) acc[p] = 0.f;
    __shared__ float xs[32][132];
    __shared__ float att[64][33];
    __shared__ float cj[32];
    __shared__ float dtj[32];
    const float* sc_base = g_scores + (size_t)bc * 65536 + (size_t)i * 256;

    // intra-chunk: sum_{j<=i} scores[i,j]*exp(cum_i-cum_j)*dt_j * x[j,:]
    for (int j0 = 0; j0 < i0 + 64; j0 += 32) {
        __syncthreads();
        for (int idx = threadIdx.x; idx < 32 * 128; idx += 256) {
            int r = idx >> 7, p = idx & 127;
            xs[r][p] = g_xbc[(size_t)(t0 + j0 + r) * CONV_DIM + h * HEADDIM + p];
        }
        if (threadIdx.x < 32) {
            int tt = t0 + j0 + threadIdx.x;
            cj[threadIdx.x]  = g_cum[tt * NHEADS + h];
            dtj[threadIdx.x] = g_dt[tt * NHEADS + h];
        }
        __syncthreads();
        #pragma unroll
        for (int q = 0; q < 8; q++) {
            int jl = pg * 8 + q;
            int j = j0 + jl;
            float a = 0.f;
            if (j <= i) a = sc_base[j] * __expf(cum_i - cj[jl]) * dtj[jl];
            att[il][jl] = a;
        }
        __syncthreads();
        #pragma unroll 4
        for (int jl = 0; jl < 32; jl++) {
            float a = att[il][jl];
            #pragma unroll
            for (int p = 0; p < 32; p++) acc[p] = fmaf(a, xs[jl][pbase + p], acc[p]);
        }
    }

    // inter-chunk: += exp(cum_i) * sum_n C[i,n] * prev[h,p,n]
    float ei = __expf(cum_i);
    float (*prevs)[132] = xs;                         // reuse (16 rows used)
    float (*Ci)[17] = (float (*)[17]) & att[0][0];    // 64x17 fits in att
    size_t pv_base = (size_t)(bc * NHEADS + h) * (HEADDIM * D_STATE);
    for (int n0 = 0; n0 < 64; n0 += 16) {
        __syncthreads();
        for (int idx = threadIdx.x; idx < 16 * 128; idx += 256) {
            int nn = idx & 15, p = idx >> 4;
            prevs[nn][p] = g_prev[pv_base + (size_t)p * 64 + n0 + nn];
        }
        for (int idx = threadIdx.x; idx < 64 * 16; idx += 256) {
            int r = idx >> 4, nn = idx & 15;
            Ci[r][nn] = g_xbc[(size_t)(t0 + i0 + r) * CONV_DIM + D_INNER + D_STATE + n0 + nn];
        }
        __syncthreads();
        #pragma unroll
        for (int nn = 0; nn < 16; nn++) {
            float cv = Ci[il][nn] * ei;
            #pragma unroll
            for (int p = 0; p < 32; p++) acc[p] = fmaf(cv, prevs[nn][pbase + p], acc[p]);
        }
    }

    float Dh = Dv[h];
    float* yout = g_y + (size_t)ti * D_INNER + h * HEADDIM + pbase;
    const float* xrow = g_xbc + (size_t)ti * CONV_DIM + h * HEADDIM + pbase;
    #pragma unroll
    for (int p = 0; p < 32; p++) yout[p] = acc[p] + Dh * xrow[p];
}

// ---------------- gating + rmsnorm (in place on g_y, tf32-rounded) -----------
__global__ void __launch_bounds__(256) gate_rms_k(const float* __restrict__ rms_w) {
    int t = blockIdx.x;
    float v[8]; float ss = 0.f, dummy = 0.f;
    const float* yrow = g_y + (size_t)t * D_INNER;
    const float* zrow = g_zx + (size_t)t * D_IN_PROJ;
    #pragma unroll
    for (int k = 0; k < 8; k++) {
        int idx = threadIdx.x + k * 256;
        float z = zrow[idx];
        float gv = yrow[idx] * (z / (1.f + __expf(-z)));
        v[k] = gv; ss += gv * gv;
    }
    block_reduce2(ss, dummy);
    float scale = rsqrtf(ss * (1.f / D_INNER) + 1e-5f);
    float* grow = g_y + (size_t)t * D_INNER;
    #pragma unroll
    for (int k = 0; k < 8; k++) {
        int idx = threadIdx.x + k * 256;
        grow[idx] = to_tf32(v[k] * scale * rms_w[idx]);
    }
}

// ---------------- host launch -------------------------------------------------
extern "C" void kernel_launch(void* const* d_in, const int* in_sizes, int n_in,
                              void* d_out, int out_size) {
    (void)in_sizes; (void)n_in; (void)out_size;
    const float* u        = (const float*)d_in[0];
    const float* in_proj  = (const float*)d_in[1];
    const float* conv_w   = (const float*)d_in[2];
    const float* conv_b   = (const float*)d_in[3];
    const float* dt_bias  = (const float*)d_in[4];
    const float* A_log    = (const float*)d_in[5];
    const float* Dv       = (const float*)d_in[6];
    const float* xnw      = (const float*)d_in[7];
    const float* xnb      = (const float*)d_in[8];
    const float* rms_w    = (const float*)d_in[9];
    const float* out_proj = (const float*)d_in[10];
    float* out = (float*)d_out;

    void *p_w1n, *p_w2n, *p_uln, *p_zx, *p_y;
    cudaGetSymbolAddress(&p_w1n, g_w1n);
    cudaGetSymbolAddress(&p_w2n, g_w2n);
    cudaGetSymbolAddress(&p_uln, g_uln);
    cudaGetSymbolAddress(&p_zx,  g_zx);
    cudaGetSymbolAddress(&p_y,   g_y);

    static int smem_set = 0;
    if (!smem_set) {
        cudaFuncSetAttribute(gemm_tf32_nt,
                             cudaFuncAttributeMaxDynamicSharedMemorySize, GEMM_SMEM);
        smem_set = 1;
    }

    l2norm_rows_k<<<D_IN_PROJ, 256>>>(in_proj, (float*)p_w1n, DIMX, 0.03125f); // fold DIM^-0.5
    l2norm_rows_k<<<DIMX, 256>>>(out_proj, (float*)p_w2n, D_INNER, 1.0f);
    layernorm_k<<<NT, 256>>>(u, xnw, xnb);

    gemm_tf32_nt<<<dim3((D_IN_PROJ + 127) / 128, NT / 128), 256, GEMM_SMEM>>>(
        (const float*)p_uln, (const float*)p_w1n, (float*)p_zx, NT, D_IN_PROJ, DIMX);

    dtcum_k<<<NBC * NHEADS, 256>>>(dt_bias, A_log);
    conv_silu_k<<<dim3(NT, (CONV_DIM + 255) / 256), 256>>>(conv_w, conv_b);
    scores_k<<<dim3(NBC, 8), 256>>>();
    states_k<<<NBC * NHEADS, 256>>>();
    chunkscan_k<<<BATCHN * NHEADS, 256>>>();
    y_k<<<dim3(NBC * NHEADS, 4), 256>>>(Dv);
    gate_rms_k<<<NT, 256>>>(rms_w);

    gemm_tf32_nt<<<dim3(DIMX / 128, NT / 128), 256, GEMM_SMEM>>>(
        (const float*)p_y, (const float*)p_w2n, out, NT, DIMX, D_INNER);
}